// round 15
// baseline (speedup 1.0000x reference)
#include <cuda_runtime.h>
#include <cuda_bf16.h>
#include <math.h>
#include <cstdint>

// ---------------- Problem constants ----------------
#define B_ 4
#define N_ 1025
#define C_ 768
#define H_ 12
#define D_ 64
#define TOPT 103
#define SCALEF 0.125f            // 64^-0.5
#define SCLOG2E (0.125f * 1.4426950408889634f)   // fold scale * log2(e) into Q

#define M_TOT (B_ * N_)          // 4100

// Output layout (float32, reference tuple flattened & concatenated):
#define OFF_OUT        0L
#define OFF_ENH_INDEX  3148800L
#define OFF_ENH_IDX    3465216L
#define OFF_FUSE_INDEX 3465628L
#define OFF_FUSE_IDX   3782044L
#define OFF_CLS        3782456L

// ---------------- Scratch (no allocation allowed) ----------------
__device__ double g_clsd[B_*(N_-1)];
__device__ double g_cls_ph[B_*H_][N_-1];
__device__ double g_cls_s[B_*H_][N_];     // raw cls scores (fp64-accurate)
__device__ float  g_u[2][B_*H_][C_];      // u = 0.125*Wk^T(Wq x0), hi/lo fp32

// bf16 2-way splits
__device__ __nv_bfloat16 g_xs[2][M_TOT*C_];
__device__ __nv_bfloat16 g_ws[2][3*C_*C_];     // w_qkv [2304,768]
__device__ __nv_bfloat16 g_wo[2][C_*C_];       // w_out [768,768]
__device__ __nv_bfloat16 g_cs[2][M_TOT*C_];    // ctx splits (written by attn)
// q/k/v as bf16 splits, [b,h,n,d]; q pre-scaled by SCALE*log2e
__device__ __nv_bfloat16 g_qs[2][B_*H_*N_*D_];
__device__ __nv_bfloat16 g_ks[2][B_*H_*N_*D_];
__device__ __nv_bfloat16 g_vs[2][B_*H_*N_*D_];

// ================= helpers =================
__device__ __forceinline__ void ldsm4(uint32_t* r, uint32_t addr) {
    asm volatile("ldmatrix.sync.aligned.m8n8.x4.shared.b16 {%0,%1,%2,%3}, [%4];"
        : "=r"(r[0]), "=r"(r[1]), "=r"(r[2]), "=r"(r[3]) : "r"(addr));
}
__device__ __forceinline__ void ldsm4t(uint32_t* r, uint32_t addr) {
    asm volatile("ldmatrix.sync.aligned.m8n8.x4.trans.shared.b16 {%0,%1,%2,%3}, [%4];"
        : "=r"(r[0]), "=r"(r[1]), "=r"(r[2]), "=r"(r[3]) : "r"(addr));
}
__device__ __forceinline__ void mma16816(float c[4], uint32_t a0, uint32_t a1,
                                         uint32_t a2, uint32_t a3,
                                         uint32_t b0, uint32_t b1) {
    asm volatile(
        "mma.sync.aligned.m16n8k16.row.col.f32.bf16.bf16.f32 "
        "{%0,%1,%2,%3}, {%4,%5,%6,%7}, {%8,%9}, {%0,%1,%2,%3};"
        : "+f"(c[0]), "+f"(c[1]), "+f"(c[2]), "+f"(c[3])
        : "r"(a0), "r"(a1), "r"(a2), "r"(a3), "r"(b0), "r"(b1));
}
__device__ __forceinline__ void cpa16(uint32_t dst, const void* src, int sz) {
    asm volatile("cp.async.cg.shared.global [%0], [%1], 16, %2;"
        :: "r"(dst), "l"(src), "r"(sz));
}
#define CP_COMMIT() asm volatile("cp.async.commit_group;" ::: "memory")
#define CP_WAIT1()  asm volatile("cp.async.wait_group 1;" ::: "memory")
// fp32 pair -> bf16x2 hi split + bf16x2 residual split (RN rounding)
__device__ __forceinline__ void split_pack(float x, float y,
                                           uint32_t& hi, uint32_t& lo) {
    asm("cvt.rn.bf16x2.f32 %0, %1, %2;" : "=r"(hi) : "f"(y), "f"(x));
    float fx = __uint_as_float(hi << 16);
    float fy = __uint_as_float(hi & 0xFFFF0000u);
    asm("cvt.rn.bf16x2.f32 %0, %1, %2;" : "=r"(lo) : "f"(y - fy), "f"(x - fx));
}

// ======================================================================
// plain split2
// ======================================================================
__global__ void split2(const float* __restrict__ src,
                       __nv_bfloat16* __restrict__ d0,
                       __nv_bfloat16* __restrict__ d1, int n) {
    int i = blockIdx.x * blockDim.x + threadIdx.x;
    if (i < n) {
        float x = src[i];
        __nv_bfloat16 b0 = __float2bfloat16(x);
        d0[i] = b0;
        d1[i] = __float2bfloat16(x - __bfloat162float(b0));
    }
}

// ======================================================================
// x-split2 fused with cls u-vector computation (blocks 0..47 = u per bh).
// u[c] = 0.125 * sum_d (W_q,h x_{b,0})[d] * W_k,h[d][c]   (fp64 -> hi/lo)
// ======================================================================
__global__ void split2_clsu(const float* __restrict__ src,
                            __nv_bfloat16* __restrict__ d0,
                            __nv_bfloat16* __restrict__ d1, int n,
                            const float* __restrict__ x,
                            const float* __restrict__ w) {
    __shared__ double q0s[64];
    if (blockIdx.x < B_ * H_) {
        const int bh = blockIdx.x;
        const int b = bh / H_, h = bh % H_;
        const int tid = threadIdx.x;
        const int wid = tid >> 5, lane = tid & 31;
        const float* xb = x + (long)b * N_ * C_;
        const float* wq = w + (long)(h * 64) * C_;
        const float* wk = w + (long)(C_ + h * 64) * C_;

        // phase 1: q0[d] fp64 (warp per d)
        for (int d = wid; d < 64; d += 8) {
            double a = 0.0;
            for (int c = lane; c < C_; c += 32)
                a += (double)xb[c] * (double)wq[(long)d * C_ + c];
            #pragma unroll
            for (int o = 16; o >= 1; o >>= 1)
                a += __shfl_xor_sync(0xffffffffu, a, o);
            if (lane == 0) q0s[d] = a;
        }
        __syncthreads();

        // phase 2: u[c] fp64 -> hi/lo fp32 to gmem
        for (int c = tid; c < C_; c += 256) {
            double a = 0.0;
            #pragma unroll 8
            for (int d = 0; d < 64; d++)
                a += q0s[d] * (double)wk[(long)d * C_ + c];
            a *= 0.125;
            float hi = (float)a;
            g_u[0][bh][c] = hi;
            g_u[1][bh][c] = (float)(a - (double)hi);
        }
        return;
    }
    int i = (blockIdx.x - B_ * H_) * 256 + threadIdx.x;
    if (i < n) {
        float v = src[i];
        __nv_bfloat16 b0 = __float2bfloat16(v);
        d0[i] = b0;
        d1[i] = __float2bfloat16(v - __bfloat162float(b0));
    }
}

// ======================================================================
// GEMM constants
// ======================================================================
#define TILE_B  (128 * 80)               // 10240 B per split tile (80B rows)
#define STAGE_G (4 * TILE_B)             // 40960 B per stage
#define MMA_SMEM (2 * STAGE_G)           // 81920 B
#define CLS_BLOCKS 192                   // 48 bh x 4 j-chunks
#define QKV_BLOCKS 594                   // 18 x 33

// ---------------- cls phase-3 chunk (inside fused launch) -------------
__device__ void cls_chunk_body(const float* __restrict__ x, char* smem) {
    float* uhi = (float*)smem;                 // 768 floats
    float* ulo = (float*)(smem + 3072);        // 768 floats
    const int id = blockIdx.x;
    const int bh = id >> 2, chunk = id & 3;
    const int b = bh / H_;
    const int tid = threadIdx.x;
    const int wid = tid >> 5, lane = tid & 31;

    const float* xb = x + (long)b * N_ * C_;
    for (int c = tid; c < C_; c += 256) {
        uhi[c] = g_u[0][bh][c];
        ulo[c] = g_u[1][bh][c];
    }
    __syncthreads();

    const int jlo = chunk * 257;
    const int jhi = min(jlo + 257, N_);
    for (int j = jlo + wid; j < jhi; j += 8) {
        const float* xr = xb + (long)j * C_;
        float sum = 0.f, comp = 0.f, err = 0.f;
        #pragma unroll 2
        for (int c = lane * 4; c < C_; c += 128) {
            float4 xv = *(const float4*)&xr[c];
            float4 uh = *(const float4*)&uhi[c];
            float4 ul = *(const float4*)&ulo[c];
            #pragma unroll
            for (int e4 = 0; e4 < 4; e4++) {
                float xe = (&xv.x)[e4], he = (&uh.x)[e4], le = (&ul.x)[e4];
                float p = he * xe;
                err = fmaf(he, xe, -p) + err;
                err = fmaf(le, xe, err);
                float y = p - comp;
                float t = sum + y;
                comp = (t - sum) - y;
                sum = t;
            }
        }
        double tot = ((double)sum - (double)comp) + (double)err;
        #pragma unroll
        for (int o = 16; o >= 1; o >>= 1)
            tot += __shfl_xor_sync(0xffffffffu, tot, o);
        if (lane == 0) g_cls_s[bh][j] = tot;
    }
}

// ======================================================================
// Fused: blocks [0,192) = cls phase-3 chunks; [192,786) = QKV GEMM.
// ======================================================================
__global__ void __launch_bounds__(256, 2)
fused_qkv_cls(const __nv_bfloat16* __restrict__ A0,
              const __nv_bfloat16* __restrict__ A1,
              const __nv_bfloat16* __restrict__ B0,
              const __nv_bfloat16* __restrict__ B1,
              const float* __restrict__ x) {
    extern __shared__ __align__(16) char smem[];
    if (blockIdx.x < CLS_BLOCKS) {
        cls_chunk_body(x, smem);
        return;
    }
    const uint32_t smb = (uint32_t)__cvta_generic_to_shared(smem);
    const int bidx = blockIdx.x - CLS_BLOCKS;
    const int m0 = (bidx / 18) * 128;
    const int n0 = (bidx % 18) * 128;
    const int tid = threadIdx.x;
    const int wid = tid >> 5, lane = tid & 31;
    const int gid = lane >> 2, tig = lane & 3;
    const int wr = wid >> 2, wc = wid & 3;

    const int lr = lane & 7;
    const int aro = lr + ((lane >> 3) & 1) * 8;
    const int aco = (lane >> 4) * 16;
    const int bro = lr + (lane >> 4) * 8;
    const int bco = ((lane >> 3) & 1) * 16;

    const __nv_bfloat16* Asrc[2] = {A0, A1};
    const __nv_bfloat16* Bsrc[2] = {B0, B1};

    float acc[4][4][4];
    #pragma unroll
    for (int i = 0; i < 4; i++)
        #pragma unroll
        for (int j = 0; j < 4; j++)
            #pragma unroll
            for (int r = 0; r < 4; r++) acc[i][j][r] = 0.f;

    auto stageg = [&](int kb_, int bufi) {
        const int kcol = kb_ * 32;
        const uint32_t sb = smb + bufi * STAGE_G;
        #pragma unroll
        for (int t = 0; t < 8; t++) {
            int idx = tid + t * 256;
            int a = idx >> 9;
            int r = (idx >> 2) & 127, c = idx & 3;
            const __nv_bfloat16* src;
            int sz = 16;
            if (a < 2) {
                src = Asrc[a] + (long)(m0 + r) * C_ + kcol + c * 8;
                if (m0 + r >= M_TOT) sz = 0;
            } else {
                src = Bsrc[a - 2] + (long)(n0 + r) * C_ + kcol + c * 8;
            }
            cpa16(sb + a * TILE_B + r * 80 + c * 16, src, sz);
        }
    };

    stageg(0, 0);
    CP_COMMIT();

    for (int kb = 0; kb < 24; kb++) {
        __syncthreads();
        if (kb + 1 < 24) stageg(kb + 1, (kb + 1) & 1);
        CP_COMMIT();
        CP_WAIT1();
        __syncthreads();

        const uint32_t sb = smb + (kb & 1) * STAGE_G;
        #pragma unroll
        for (int ks = 0; ks < 2; ks++) {
            #pragma unroll
            for (int sa = 0; sa < 2; sa++) {
                uint32_t af[4][4];
                #pragma unroll
                for (int i = 0; i < 4; i++)
                    ldsm4(af[i], sb + sa * TILE_B +
                          (uint32_t)((wr * 64 + i * 16 + aro) * 80 + ks * 32 + aco));
                #pragma unroll
                for (int sb2 = 0; sb2 < 2 - sa; sb2++) {
                    uint32_t bf[4][2], r4[4];
                    ldsm4(r4, sb + (2 + sb2) * TILE_B +
                          (uint32_t)((wc * 32 + bro) * 80 + ks * 32 + bco));
                    bf[0][0] = r4[0]; bf[0][1] = r4[1];
                    bf[1][0] = r4[2]; bf[1][1] = r4[3];
                    ldsm4(r4, sb + (2 + sb2) * TILE_B +
                          (uint32_t)((wc * 32 + 16 + bro) * 80 + ks * 32 + bco));
                    bf[2][0] = r4[0]; bf[2][1] = r4[1];
                    bf[3][0] = r4[2]; bf[3][1] = r4[3];
                    #pragma unroll
                    for (int i = 0; i < 4; i++)
                        #pragma unroll
                        for (int j = 0; j < 4; j++)
                            mma16816(acc[i][j], af[i][0], af[i][1], af[i][2],
                                     af[i][3], bf[j][0], bf[j][1]);
                }
            }
        }
    }

    // epilogue: scatter q/k/v bf16 splits (q pre-scaled)
    #pragma unroll
    for (int i = 0; i < 4; i++) {
        #pragma unroll
        for (int half = 0; half < 2; half++) {
            int gm = m0 + wr * 64 + i * 16 + gid + half * 8;
            if (gm >= M_TOT) continue;
            int btok = gm / N_, nt = gm % N_;
            #pragma unroll
            for (int j = 0; j < 4; j++) {
                float v0 = acc[i][j][half * 2];
                float v1 = acc[i][j][half * 2 + 1];
                int jg = n0 + wc * 32 + j * 8 + tig * 2;
                int qkv_i = jg / C_;
                int rem = jg % C_;
                int h = rem >> 6, d0 = rem & 63;
                if (qkv_i == 0) { v0 *= SCLOG2E; v1 *= SCLOG2E; }
                __nv_bfloat16* dh = (qkv_i == 0) ? g_qs[0]
                                    : (qkv_i == 1 ? g_ks[0] : g_vs[0]);
                __nv_bfloat16* dl = (qkv_i == 0) ? g_qs[1]
                                    : (qkv_i == 1 ? g_ks[1] : g_vs[1]);
                long base = ((long)(btok * H_ + h) * N_ + nt) * 64 + d0;
                uint32_t hi, lo;
                split_pack(v0, v1, hi, lo);
                *(uint32_t*)&dh[base] = hi;
                *(uint32_t*)&dl[base] = lo;
            }
        }
    }
}

// ======================================================================
// out projection GEMM
// ======================================================================
__global__ void __launch_bounds__(256, 2)
out_gemm(const __nv_bfloat16* __restrict__ A0, const __nv_bfloat16* __restrict__ A1,
         const __nv_bfloat16* __restrict__ B0, const __nv_bfloat16* __restrict__ B1,
         const float* __restrict__ bias, float* __restrict__ out) {
    extern __shared__ __align__(16) char smem[];
    const uint32_t smb = (uint32_t)__cvta_generic_to_shared(smem);
    const int tid = threadIdx.x;
    const int wid = tid >> 5, lane = tid & 31;
    const int gid = lane >> 2, tig = lane & 3;
    const int wr = wid >> 2, wc = wid & 3;
    const int m0 = blockIdx.y * 128;
    const int n0 = blockIdx.x * 128;

    const int lr = lane & 7;
    const int aro = lr + ((lane >> 3) & 1) * 8;
    const int aco = (lane >> 4) * 16;
    const int bro = lr + (lane >> 4) * 8;
    const int bco = ((lane >> 3) & 1) * 16;

    const __nv_bfloat16* Asrc[2] = {A0, A1};
    const __nv_bfloat16* Bsrc[2] = {B0, B1};

    float acc[4][4][4];
    #pragma unroll
    for (int i = 0; i < 4; i++)
        #pragma unroll
        for (int j = 0; j < 4; j++)
            #pragma unroll
            for (int r = 0; r < 4; r++) acc[i][j][r] = 0.f;

    auto stageg = [&](int kb_, int bufi) {
        const int kcol = kb_ * 32;
        const uint32_t sb = smb + bufi * STAGE_G;
        #pragma unroll
        for (int t = 0; t < 8; t++) {
            int idx = tid + t * 256;
            int a = idx >> 9;
            int r = (idx >> 2) & 127, c = idx & 3;
            const __nv_bfloat16* src;
            int sz = 16;
            if (a < 2) {
                src = Asrc[a] + (long)(m0 + r) * C_ + kcol + c * 8;
                if (m0 + r >= M_TOT) sz = 0;
            } else {
                src = Bsrc[a - 2] + (long)(n0 + r) * C_ + kcol + c * 8;
            }
            cpa16(sb + a * TILE_B + r * 80 + c * 16, src, sz);
        }
    };

    stageg(0, 0);
    CP_COMMIT();

    for (int kb = 0; kb < 24; kb++) {
        __syncthreads();
        if (kb + 1 < 24) stageg(kb + 1, (kb + 1) & 1);
        CP_COMMIT();
        CP_WAIT1();
        __syncthreads();

        const uint32_t sb = smb + (kb & 1) * STAGE_G;
        #pragma unroll
        for (int ks = 0; ks < 2; ks++) {
            #pragma unroll
            for (int sa = 0; sa < 2; sa++) {
                uint32_t af[4][4];
                #pragma unroll
                for (int i = 0; i < 4; i++)
                    ldsm4(af[i], sb + sa * TILE_B +
                          (uint32_t)((wr * 64 + i * 16 + aro) * 80 + ks * 32 + aco));
                #pragma unroll
                for (int sb2 = 0; sb2 < 2 - sa; sb2++) {
                    uint32_t bf[4][2], r4[4];
                    ldsm4(r4, sb + (2 + sb2) * TILE_B +
                          (uint32_t)((wc * 32 + bro) * 80 + ks * 32 + bco));
                    bf[0][0] = r4[0]; bf[0][1] = r4[1];
                    bf[1][0] = r4[2]; bf[1][1] = r4[3];
                    ldsm4(r4, sb + (2 + sb2) * TILE_B +
                          (uint32_t)((wc * 32 + 16 + bro) * 80 + ks * 32 + bco));
                    bf[2][0] = r4[0]; bf[2][1] = r4[1];
                    bf[3][0] = r4[2]; bf[3][1] = r4[3];
                    #pragma unroll
                    for (int i = 0; i < 4; i++)
                        #pragma unroll
                        for (int j = 0; j < 4; j++)
                            mma16816(acc[i][j], af[i][0], af[i][1], af[i][2],
                                     af[i][3], bf[j][0], bf[j][1]);
                }
            }
        }
    }

    #pragma unroll
    for (int i = 0; i < 4; i++) {
        #pragma unroll
        for (int half = 0; half < 2; half++) {
            int gm = m0 + wr * 64 + i * 16 + gid + half * 8;
            if (gm >= M_TOT) continue;
            #pragma unroll
            for (int j = 0; j < 4; j++) {
                int jg = n0 + wc * 32 + j * 8 + tig * 2;
                long base = OFF_OUT + (long)gm * C_ + jg;
                *(float2*)&out[base] = make_float2(
                    acc[i][j][half*2]   + bias[jg],
                    acc[i][j][half*2+1] + bias[jg + 1]);
            }
        }
    }
}

// ======================================================================
// mma.sync flash attention (unchanged from R14).
// ======================================================================
#define TILE_A  9216
#define STAGE_A (4 * TILE_A)             // 36864 B per stage
#define QREG_B  (2 * 128 * 144)          // 36864 B (Q hi+lo)
#define ATTN_SMEM3 (QREG_B + 2 * STAGE_A)  // 110592 B

__global__ void __launch_bounds__(256, 2)
attn_mma() {
    extern __shared__ __align__(16) uint32_t asw[];
    const uint32_t smb = (uint32_t)__cvta_generic_to_shared(asw);
    const int tid = threadIdx.x;
    const int wid = tid >> 5, lane = tid & 31;
    const int gid = lane >> 2, tig = lane & 3;
    const int bh = blockIdx.y;
    const int q0g = blockIdx.x * 128;

    const int lr = lane & 7;
    const int aro = lr + ((lane >> 3) & 1) * 8;
    const int aco = (lane >> 4) * 16;
    const int bro = lr + (lane >> 4) * 8;
    const int bco = ((lane >> 3) & 1) * 16;
    const int vro = lr + ((lane >> 3) & 1) * 8;
    const int vco = (lane >> 4) * 16;

    const __nv_bfloat16* Qh = g_qs[0] + (long)bh * N_ * 64;
    const __nv_bfloat16* Ql = g_qs[1] + (long)bh * N_ * 64;
    const __nv_bfloat16* Kh = g_ks[0] + (long)bh * N_ * 64;
    const __nv_bfloat16* Kl = g_ks[1] + (long)bh * N_ * 64;
    const __nv_bfloat16* Vh = g_vs[0] + (long)bh * N_ * 64;
    const __nv_bfloat16* Vl = g_vs[1] + (long)bh * N_ * 64;

    {
        __nv_bfloat16* Q0 = (__nv_bfloat16*)asw;
        __nv_bfloat16* Q1 = (__nv_bfloat16*)((char*)asw + 18432);
        for (int idx = tid; idx < 128 * 8; idx += 256) {
            int r = idx >> 3, c = idx & 7;
            int qi = q0g + r;
            uint4 vh = make_uint4(0, 0, 0, 0), vl = vh;
            if (qi < N_) {
                vh = *(const uint4*)(Qh + (long)qi * 64 + c * 8);
                vl = *(const uint4*)(Ql + (long)qi * 64 + c * 8);
            }
            *(uint4*)(Q0 + r * 72 + c * 8) = vh;
            *(uint4*)(Q1 + r * 72 + c * 8) = vl;
        }
    }

    float accD[8][4];
    #pragma unroll
    for (int dt = 0; dt < 8; dt++)
        #pragma unroll
        for (int r = 0; r < 4; r++) accD[dt][r] = 0.f;
    float m2[2] = {-INFINITY, -INFINITY};
    float l2[2] = {0.f, 0.f};

    const int rlo = q0g + wid * 16;
    const bool w_dead = (rlo >= N_);
    bool wq_uni = false; int wqb = -2;
    int wblk_lo = 5, wblk_hi = -5;
    if (!w_dead) {
        int rhi = min(rlo + 15, N_ - 1);
        int blo = (max(rlo, 1) - 1) >> 8;
        int bhi = (rhi >= 1) ? ((rhi - 1) >> 8) : -1;
        wblk_lo = blo; wblk_hi = bhi;
        if (rlo >= 1 && blo == bhi) { wq_uni = true; wqb = blo; }
    }
    const int row0g = rlo + gid, row1g = rlo + gid + 8;
    const int qb0 = (row0g >= 1 && row0g < N_) ? ((row0g - 1) >> 8) : -1;
    const int qb1 = (row1g >= 1 && row1g < N_) ? ((row1g - 1) >> 8) : -1;

    auto stagea = [&](int kt_, int bufi) {
        const int k0 = kt_ * 64;
        const uint32_t sb = smb + QREG_B + bufi * STAGE_A;
        const __nv_bfloat16* srcs[4] = {Kh, Kl, Vh, Vl};
        #pragma unroll
        for (int t = 0; t < 8; t++) {
            int idx = tid + t * 256;
            int a = idx >> 9, r = (idx >> 3) & 63, c = idx & 7;
            int kj = k0 + r;
            const __nv_bfloat16* src = srcs[a] + (long)kj * 64 + c * 8;
            cpa16(sb + a * TILE_A + r * 144 + c * 16, src, (kj < N_) ? 16 : 0);
        }
    };

    stagea(0, 0);
    CP_COMMIT();
    __syncthreads();

    for (int kt = 0; kt < 17; kt++) {
        const int k0g = kt * 64;
        __syncthreads();
        if (kt + 1 < 17) stagea(kt + 1, (kt + 1) & 1);
        CP_COMMIT();
        CP_WAIT1();
        __syncthreads();

        bool skip = w_dead;
        bool need_mask = false;
        if (!skip) {
            int klo = max(k0g, 1), khi = min(k0g + 63, N_ - 1);
            int kbl = (klo - 1) >> 8, kbh = (khi - 1) >> 8;
            if (wq_uni && k0g >= 1 && kbl == kbh && kbl == wqb) skip = true;
            else need_mask = (k0g + 63 >= N_) ||
                             (kbl <= wblk_hi && kbh >= wblk_lo);
        }
        if (skip) continue;

        const uint32_t sb = smb + QREG_B + (kt & 1) * STAGE_A;

        float sp[8][4];
        #pragma unroll
        for (int nt = 0; nt < 8; nt++)
            #pragma unroll
            for (int r = 0; r < 4; r++) sp[nt][r] = 0.f;

        #pragma unroll
        for (int ks = 0; ks < 4; ks++) {
            uint32_t qh4[4], ql4[4];
            uint32_t qoff = (uint32_t)((wid * 16 + aro) * 144 + ks * 32 + aco);
            ldsm4(qh4, smb + qoff);
            ldsm4(ql4, smb + 18432 + qoff);
            #pragma unroll
            for (int ntp = 0; ntp < 4; ntp++) {
                uint32_t rowb = (uint32_t)((ntp * 16 + bro) * 144 + ks * 32 + bco);
                uint32_t h4[4], l4[4];
                ldsm4(h4, sb + rowb);
                ldsm4(l4, sb + TILE_A + rowb);
                mma16816(sp[2*ntp], qh4[0], qh4[1], qh4[2], qh4[3], h4[0], h4[1]);
                mma16816(sp[2*ntp], ql4[0], ql4[1], ql4[2], ql4[3], h4[0], h4[1]);
                mma16816(sp[2*ntp], qh4[0], qh4[1], qh4[2], qh4[3], l4[0], l4[1]);
                mma16816(sp[2*ntp+1], qh4[0], qh4[1], qh4[2], qh4[3], h4[2], h4[3]);
                mma16816(sp[2*ntp+1], ql4[0], ql4[1], ql4[2], ql4[3], h4[2], h4[3]);
                mma16816(sp[2*ntp+1], qh4[0], qh4[1], qh4[2], qh4[3], l4[2], l4[3]);
            }
        }

        if (need_mask) {
            #pragma unroll
            for (int nt = 0; nt < 8; nt++) {
                #pragma unroll
                for (int c = 0; c < 4; c++) {
                    int qb = (c >= 2) ? qb1 : qb0;
                    int key = k0g + nt * 8 + 2 * tig + (c & 1);
                    bool bad = (key >= N_) ||
                               (qb >= 0 && key >= 1 && ((key - 1) >> 8) == qb);
                    if (bad) sp[nt][c] = -INFINITY;
                }
            }
        }

        #pragma unroll
        for (int half = 0; half < 2; half++) {
            float mx = -INFINITY;
            #pragma unroll
            for (int nt = 0; nt < 8; nt++)
                mx = fmaxf(mx, fmaxf(sp[nt][half*2], sp[nt][half*2+1]));
            mx = fmaxf(mx, __shfl_xor_sync(0xffffffffu, mx, 1));
            mx = fmaxf(mx, __shfl_xor_sync(0xffffffffu, mx, 2));
            float mnew = fmaxf(m2[half], mx);
            float corr = exp2f(m2[half] - mnew);
            m2[half] = mnew;
            float rs = 0.f;
            #pragma unroll
            for (int nt = 0; nt < 8; nt++) {
                float p0 = exp2f(sp[nt][half*2]   - mnew);
                float p1 = exp2f(sp[nt][half*2+1] - mnew);
                sp[nt][half*2] = p0; sp[nt][half*2+1] = p1;
                rs += p0 + p1;
            }
            rs += __shfl_xor_sync(0xffffffffu, rs, 1);
            rs += __shfl_xor_sync(0xffffffffu, rs, 2);
            l2[half] = l2[half] * corr + rs;
            #pragma unroll
            for (int dt = 0; dt < 8; dt++) {
                accD[dt][half*2]   *= corr;
                accD[dt][half*2+1] *= corr;
            }
        }

        #pragma unroll
        for (int ks = 0; ks < 4; ks++) {
            uint32_t p0[4], p1[4];
            split_pack(sp[2*ks][0],   sp[2*ks][1],   p0[0], p1[0]);
            split_pack(sp[2*ks][2],   sp[2*ks][3],   p0[1], p1[1]);
            split_pack(sp[2*ks+1][0], sp[2*ks+1][1], p0[2], p1[2]);
            split_pack(sp[2*ks+1][2], sp[2*ks+1][3], p0[3], p1[3]);
            #pragma unroll
            for (int dtp = 0; dtp < 4; dtp++) {
                uint32_t rowb = (uint32_t)((ks * 16 + vro) * 144 + dtp * 32 + vco);
                uint32_t h4[4], l4[4];
                ldsm4t(h4, sb + 2 * TILE_A + rowb);
                ldsm4t(l4, sb + 3 * TILE_A + rowb);
                mma16816(accD[2*dtp], p0[0], p0[1], p0[2], p0[3], h4[0], h4[1]);
                mma16816(accD[2*dtp], p1[0], p1[1], p1[2], p1[3], h4[0], h4[1]);
                mma16816(accD[2*dtp], p0[0], p0[1], p0[2], p0[3], l4[0], l4[1]);
                mma16816(accD[2*dtp+1], p0[0], p0[1], p0[2], p0[3], h4[2], h4[3]);
                mma16816(accD[2*dtp+1], p1[0], p1[1], p1[2], p1[3], h4[2], h4[3]);
                mma16816(accD[2*dtp+1], p0[0], p0[1], p0[2], p0[3], l4[2], l4[3]);
            }
        }
    }

    const int b = bh / H_, h = bh % H_;
    #pragma unroll
    for (int half = 0; half < 2; half++) {
        int row = rlo + gid + half * 8;
        if (row < N_) {
            float inv = 1.f / l2[half];
            #pragma unroll
            for (int dt = 0; dt < 8; dt++) {
                int d = dt * 8 + 2 * tig;
                long base = ((long)b * N_ + row) * C_ + h * 64 + d;
                uint32_t hi, lo;
                split_pack(accD[dt][half*2] * inv, accD[dt][half*2+1] * inv, hi, lo);
                *(uint32_t*)&g_cs[0][base] = hi;
                *(uint32_t*)&g_cs[1][base] = lo;
            }
        }
    }
}

// ======================================================================
// cls softmax over precomputed scores (fp64). One CTA per (b,h).
// ======================================================================
__global__ void __launch_bounds__(1024)
cls_soft_kernel() {
    __shared__ double s[N_];
    __shared__ double red[32];
    const int bh = blockIdx.x;
    const int tid = threadIdx.x;
    const int wid = tid >> 5, lane = tid & 31;

    for (int j = tid; j < N_; j += 1024) s[j] = g_cls_s[bh][j];
    __syncthreads();

    double lm = -1e300;
    for (int j = tid; j < N_; j += 1024) lm = fmax(lm, s[j]);
    #pragma unroll
    for (int o = 16; o >= 1; o >>= 1)
        lm = fmax(lm, __shfl_xor_sync(0xffffffffu, lm, o));
    if (lane == 0) red[wid] = lm;
    __syncthreads();
    if (wid == 0) {
        double t = red[lane];
        #pragma unroll
        for (int o = 16; o >= 1; o >>= 1)
            t = fmax(t, __shfl_xor_sync(0xffffffffu, t, o));
        if (lane == 0) red[0] = t;
    }
    __syncthreads();
    const double m = red[0];
    __syncthreads();

    double ls = 0.0;
    for (int j = tid; j < N_; j += 1024) {
        double e = exp(s[j] - m);
        s[j] = e;
        ls += e;
    }
    #pragma unroll
    for (int o = 16; o >= 1; o >>= 1)
        ls += __shfl_xor_sync(0xffffffffu, ls, o);
    if (lane == 0) red[wid] = ls;
    __syncthreads();
    if (wid == 0) {
        double t = red[lane];
        #pragma unroll
        for (int o = 16; o >= 1; o >>= 1)
            t += __shfl_xor_sync(0xffffffffu, t, o);
        if (lane == 0) red[0] = t;
    }
    __syncthreads();
    const double inv = 1.0 / red[0];

    for (int j = tid; j < N_ - 1; j += 1024)
        g_cls_ph[bh][j] = s[j + 1] * inv;
}

// ======================================================================
// head-mean reduce (fp64, h-ascending). One CTA per batch.
// ======================================================================
__global__ void cls_reduce_kernel(float* __restrict__ out) {
    const int b = blockIdx.x, tid = threadIdx.x;
    for (int j = tid; j < N_ - 1; j += 256) {
        double a = 0.0;
        #pragma unroll
        for (int h = 0; h < H_; h++)
            a += g_cls_ph[b * H_ + h][j] * (1.0 / 12.0);
        g_clsd[b * (N_ - 1) + j] = a;
        out[OFF_CLS + (long)b * (N_ - 1) + j] = (float)a;
    }
}

// ======================================================================
// dual bitonic top-k (103 of 1024) on fp64 keys, jax tie-break.
// ======================================================================
__global__ void sort_kernel(float* __restrict__ out) {
    __shared__ double v[1024];
    __shared__ int ix[1024];
    const int b = blockIdx.x, tid = threadIdx.x;

    for (int pass = 0; pass < 2; pass++) {
        __syncthreads();
        for (int i = tid; i < 1024; i += 512) {
            v[i] = g_clsd[b * 1024 + i];
            ix[i] = i;
        }
        __syncthreads();
        const bool desc = (pass == 0);
        for (int k = 2; k <= 1024; k <<= 1) {
            for (int j = k >> 1; j > 0; j >>= 1) {
                for (int i = tid; i < 1024; i += 512) {
                    int p = i ^ j;
                    if (p > i) {
                        double va = v[i], vb = v[p];
                        int ia = ix[i], ib = ix[p];
                        bool ab = desc ? (va > vb || (va == vb && ia < ib))
                                       : (va < vb || (va == vb && ia < ib));
                        bool up = ((i & k) == 0);
                        if (up ? !ab : ab) {
                            v[i] = vb; v[p] = va;
                            ix[i] = ib; ix[p] = ia;
                        }
                    }
                }
                __syncthreads();
            }
        }
        const long offIdx = desc ? OFF_ENH_IDX : OFF_FUSE_IDX;
        const long offBrd = desc ? OFF_ENH_INDEX : OFF_FUSE_INDEX;
        for (int t = tid; t < TOPT; t += 512)
            out[offIdx + (long)b * TOPT + t] = (float)ix[t];
        for (int e = tid; e < TOPT * C_; e += 512) {
            int t = e / C_;
            out[offBrd + ((long)b * TOPT + t) * C_ + (e % C_)] = (float)ix[t];
        }
    }
}

// ======================================================================
// Launch
// ======================================================================
extern "C" void kernel_launch(void* const* d_in, const int* in_sizes, int n_in,
                              void* d_out, int out_size) {
    const float* x     = (const float*)d_in[0];
    const float* w_qkv = (const float*)d_in[1];
    const float* w_out = (const float*)d_in[2];
    const float* b_out = (const float*)d_in[3];
    float* out = (float*)d_out;

    cudaFuncSetAttribute(fused_qkv_cls, cudaFuncAttributeMaxDynamicSharedMemorySize,
                         MMA_SMEM);
    cudaFuncSetAttribute(out_gemm, cudaFuncAttributeMaxDynamicSharedMemorySize,
                         MMA_SMEM);
    cudaFuncSetAttribute(attn_mma, cudaFuncAttributeMaxDynamicSharedMemorySize,
                         ATTN_SMEM3);

    __nv_bfloat16 *xs0, *xs1, *ws0, *ws1, *wo0, *wo1, *cs0, *cs1;
    cudaGetSymbolAddress((void**)&xs0, g_xs); xs1 = xs0 + (long)M_TOT*C_;
    cudaGetSymbolAddress((void**)&ws0, g_ws); ws1 = ws0 + (long)3*C_*C_;
    cudaGetSymbolAddress((void**)&wo0, g_wo); wo1 = wo0 + (long)C_*C_;
    cudaGetSymbolAddress((void**)&cs0, g_cs); cs1 = cs0 + (long)M_TOT*C_;

    // x split fused with cls u-vector (blocks 0..47)
    split2_clsu<<<B_ * H_ + (M_TOT*C_ + 255)/256, 256>>>(
        x, xs0, xs1, M_TOT*C_, x, w_qkv);
    split2<<<(3*C_*C_ + 255)/256, 256>>>(w_qkv, ws0, ws1, 3*C_*C_);
    split2<<<(C_*C_ + 255)/256, 256>>>(w_out, wo0, wo1, C_*C_);

    // fused: cls phase-3 chunks (0..191) + QKV GEMM (192..785)
    fused_qkv_cls<<<CLS_BLOCKS + QKV_BLOCKS, 256, MMA_SMEM>>>(
        xs0, xs1, ws0, ws1, x);

    // attention -> ctx bf16 splits directly
    attn_mma<<<dim3((N_ + 127)/128, B_ * H_), 256, ATTN_SMEM3>>>();

    // OUT: [4100,768] = ctx @ w_out^T + bias
    out_gemm<<<dim3(C_/128, (M_TOT + 127)/128), 256, MMA_SMEM>>>(
        cs0, cs1, wo0, wo1, b_out, out);

    // cls tail: fp64 softmax over precomputed scores, mean, top-k
    cls_soft_kernel<<<B_ * H_, 1024>>>();
    cls_reduce_kernel<<<B_, 256>>>(out);
    sort_kernel<<<B_, 512>>>(out);
}

// round 16
// speedup vs baseline: 1.0003x; 1.0003x over previous
#include <cuda_runtime.h>
#include <cuda_bf16.h>
#include <math.h>
#include <cstdint>

// ---------------- Problem constants ----------------
#define B_ 4
#define N_ 1025
#define C_ 768
#define H_ 12
#define D_ 64
#define TOPT 103
#define SCALEF 0.125f            // 64^-0.5
#define SCLOG2E (0.125f * 1.4426950408889634f)   // fold scale * log2(e) into Q

#define M_TOT (B_ * N_)          // 4100

// Output layout (float32, reference tuple flattened & concatenated):
#define OFF_OUT        0L
#define OFF_ENH_INDEX  3148800L
#define OFF_ENH_IDX    3465216L
#define OFF_FUSE_INDEX 3465628L
#define OFF_FUSE_IDX   3782044L
#define OFF_CLS        3782456L

// ---------------- Scratch (no allocation allowed) ----------------
__device__ double g_clsd[B_*(N_-1)];
__device__ double g_cls_ph[B_*H_][N_-1];
__device__ double g_cls_s[B_*H_][N_];     // raw cls scores (fp64-accurate)
__device__ float  g_u[2][B_*H_][C_];      // u = 0.125*Wk^T(Wq x0), hi/lo fp32

// bf16 2-way splits
__device__ __nv_bfloat16 g_xs[2][M_TOT*C_];
__device__ __nv_bfloat16 g_ws[2][3*C_*C_];     // w_qkv [2304,768]
__device__ __nv_bfloat16 g_wo[2][C_*C_];       // w_out [768,768]
__device__ __nv_bfloat16 g_cs[2][M_TOT*C_];    // ctx splits (written by attn)
// q/k/v as bf16 splits, [b,h,n,d]; q pre-scaled by SCALE*log2e
__device__ __nv_bfloat16 g_qs[2][B_*H_*N_*D_];
__device__ __nv_bfloat16 g_ks[2][B_*H_*N_*D_];
__device__ __nv_bfloat16 g_vs[2][B_*H_*N_*D_];

// ================= helpers =================
__device__ __forceinline__ void ldsm4(uint32_t* r, uint32_t addr) {
    asm volatile("ldmatrix.sync.aligned.m8n8.x4.shared.b16 {%0,%1,%2,%3}, [%4];"
        : "=r"(r[0]), "=r"(r[1]), "=r"(r[2]), "=r"(r[3]) : "r"(addr));
}
__device__ __forceinline__ void ldsm4t(uint32_t* r, uint32_t addr) {
    asm volatile("ldmatrix.sync.aligned.m8n8.x4.trans.shared.b16 {%0,%1,%2,%3}, [%4];"
        : "=r"(r[0]), "=r"(r[1]), "=r"(r[2]), "=r"(r[3]) : "r"(addr));
}
__device__ __forceinline__ void mma16816(float c[4], uint32_t a0, uint32_t a1,
                                         uint32_t a2, uint32_t a3,
                                         uint32_t b0, uint32_t b1) {
    asm volatile(
        "mma.sync.aligned.m16n8k16.row.col.f32.bf16.bf16.f32 "
        "{%0,%1,%2,%3}, {%4,%5,%6,%7}, {%8,%9}, {%0,%1,%2,%3};"
        : "+f"(c[0]), "+f"(c[1]), "+f"(c[2]), "+f"(c[3])
        : "r"(a0), "r"(a1), "r"(a2), "r"(a3), "r"(b0), "r"(b1));
}
__device__ __forceinline__ void cpa16(uint32_t dst, const void* src, int sz) {
    asm volatile("cp.async.cg.shared.global [%0], [%1], 16, %2;"
        :: "r"(dst), "l"(src), "r"(sz));
}
#define CP_COMMIT() asm volatile("cp.async.commit_group;" ::: "memory")
#define CP_WAIT1()  asm volatile("cp.async.wait_group 1;" ::: "memory")
// fp32 pair -> bf16x2 hi split + bf16x2 residual split (RN rounding)
__device__ __forceinline__ void split_pack(float x, float y,
                                           uint32_t& hi, uint32_t& lo) {
    asm("cvt.rn.bf16x2.f32 %0, %1, %2;" : "=r"(hi) : "f"(y), "f"(x));
    float fx = __uint_as_float(hi << 16);
    float fy = __uint_as_float(hi & 0xFFFF0000u);
    asm("cvt.rn.bf16x2.f32 %0, %1, %2;" : "=r"(lo) : "f"(y - fy), "f"(x - fx));
}

// ======================================================================
// plain split2 (lean, memory-bound)
// ======================================================================
__global__ void split2(const float* __restrict__ src,
                       __nv_bfloat16* __restrict__ d0,
                       __nv_bfloat16* __restrict__ d1, int n) {
    int i = blockIdx.x * blockDim.x + threadIdx.x;
    if (i < n) {
        float x = src[i];
        __nv_bfloat16 b0 = __float2bfloat16(x);
        d0[i] = b0;
        d1[i] = __float2bfloat16(x - __bfloat162float(b0));
    }
}

// ======================================================================
// cls u-vector kernel (own launch, 48 blocks -> no occupancy tax on splits)
// u[c] = 0.125 * sum_d (W_q,h x_{b,0})[d] * W_k,h[d][c]   (fp64 -> hi/lo)
// ======================================================================
__global__ void __launch_bounds__(256)
cls_u_kernel(const float* __restrict__ x, const float* __restrict__ w) {
    __shared__ double q0s[64];
    const int bh = blockIdx.x;
    const int b = bh / H_, h = bh % H_;
    const int tid = threadIdx.x;
    const int wid = tid >> 5, lane = tid & 31;
    const float* xb = x + (long)b * N_ * C_;
    const float* wq = w + (long)(h * 64) * C_;
    const float* wk = w + (long)(C_ + h * 64) * C_;

    // phase 1: q0[d] fp64 (warp per d)
    for (int d = wid; d < 64; d += 8) {
        double a = 0.0;
        for (int c = lane; c < C_; c += 32)
            a += (double)xb[c] * (double)wq[(long)d * C_ + c];
        #pragma unroll
        for (int o = 16; o >= 1; o >>= 1)
            a += __shfl_xor_sync(0xffffffffu, a, o);
        if (lane == 0) q0s[d] = a;
    }
    __syncthreads();

    // phase 2: u[c] fp64 -> hi/lo fp32 to gmem
    for (int c = tid; c < C_; c += 256) {
        double a = 0.0;
        #pragma unroll 8
        for (int d = 0; d < 64; d++)
            a += q0s[d] * (double)wk[(long)d * C_ + c];
        a *= 0.125;
        float hi = (float)a;
        g_u[0][bh][c] = hi;
        g_u[1][bh][c] = (float)(a - (double)hi);
    }
}

// ======================================================================
// GEMM constants
// ======================================================================
#define TILE_B  (128 * 80)               // 10240 B per split tile (80B rows)
#define STAGE_G (4 * TILE_B)             // 40960 B per stage
#define MMA_SMEM (2 * STAGE_G)           // 81920 B
#define CLS_BLOCKS 192                   // 48 bh x 4 j-chunks
#define QKV_BLOCKS 594                   // 18 x 33

// ---------------- cls phase-3 chunk (inside fused launch) -------------
__device__ void cls_chunk_body(const float* __restrict__ x, char* smem) {
    float* uhi = (float*)smem;                 // 768 floats
    float* ulo = (float*)(smem + 3072);        // 768 floats
    const int id = blockIdx.x;
    const int bh = id >> 2, chunk = id & 3;
    const int b = bh / H_;
    const int tid = threadIdx.x;
    const int wid = tid >> 5, lane = tid & 31;

    const float* xb = x + (long)b * N_ * C_;
    for (int c = tid; c < C_; c += 256) {
        uhi[c] = g_u[0][bh][c];
        ulo[c] = g_u[1][bh][c];
    }
    __syncthreads();

    const int jlo = chunk * 257;
    const int jhi = min(jlo + 257, N_);
    for (int j = jlo + wid; j < jhi; j += 8) {
        const float* xr = xb + (long)j * C_;
        float sum = 0.f, comp = 0.f, err = 0.f;
        #pragma unroll 2
        for (int c = lane * 4; c < C_; c += 128) {
            float4 xv = *(const float4*)&xr[c];
            float4 uh = *(const float4*)&uhi[c];
            float4 ul = *(const float4*)&ulo[c];
            #pragma unroll
            for (int e4 = 0; e4 < 4; e4++) {
                float xe = (&xv.x)[e4], he = (&uh.x)[e4], le = (&ul.x)[e4];
                float p = he * xe;
                err = fmaf(he, xe, -p) + err;
                err = fmaf(le, xe, err);
                float y = p - comp;
                float t = sum + y;
                comp = (t - sum) - y;
                sum = t;
            }
        }
        double tot = ((double)sum - (double)comp) + (double)err;
        #pragma unroll
        for (int o = 16; o >= 1; o >>= 1)
            tot += __shfl_xor_sync(0xffffffffu, tot, o);
        if (lane == 0) g_cls_s[bh][j] = tot;
    }
}

// ======================================================================
// Fused: blocks [0,192) = cls phase-3 chunks; [192,786) = QKV GEMM.
// ======================================================================
__global__ void __launch_bounds__(256, 2)
fused_qkv_cls(const __nv_bfloat16* __restrict__ A0,
              const __nv_bfloat16* __restrict__ A1,
              const __nv_bfloat16* __restrict__ B0,
              const __nv_bfloat16* __restrict__ B1,
              const float* __restrict__ x) {
    extern __shared__ __align__(16) char smem[];
    if (blockIdx.x < CLS_BLOCKS) {
        cls_chunk_body(x, smem);
        return;
    }
    const uint32_t smb = (uint32_t)__cvta_generic_to_shared(smem);
    const int bidx = blockIdx.x - CLS_BLOCKS;
    const int m0 = (bidx / 18) * 128;
    const int n0 = (bidx % 18) * 128;
    const int tid = threadIdx.x;
    const int wid = tid >> 5, lane = tid & 31;
    const int gid = lane >> 2, tig = lane & 3;
    const int wr = wid >> 2, wc = wid & 3;

    const int lr = lane & 7;
    const int aro = lr + ((lane >> 3) & 1) * 8;
    const int aco = (lane >> 4) * 16;
    const int bro = lr + (lane >> 4) * 8;
    const int bco = ((lane >> 3) & 1) * 16;

    const __nv_bfloat16* Asrc[2] = {A0, A1};
    const __nv_bfloat16* Bsrc[2] = {B0, B1};

    float acc[4][4][4];
    #pragma unroll
    for (int i = 0; i < 4; i++)
        #pragma unroll
        for (int j = 0; j < 4; j++)
            #pragma unroll
            for (int r = 0; r < 4; r++) acc[i][j][r] = 0.f;

    auto stageg = [&](int kb_, int bufi) {
        const int kcol = kb_ * 32;
        const uint32_t sb = smb + bufi * STAGE_G;
        #pragma unroll
        for (int t = 0; t < 8; t++) {
            int idx = tid + t * 256;
            int a = idx >> 9;
            int r = (idx >> 2) & 127, c = idx & 3;
            const __nv_bfloat16* src;
            int sz = 16;
            if (a < 2) {
                src = Asrc[a] + (long)(m0 + r) * C_ + kcol + c * 8;
                if (m0 + r >= M_TOT) sz = 0;
            } else {
                src = Bsrc[a - 2] + (long)(n0 + r) * C_ + kcol + c * 8;
            }
            cpa16(sb + a * TILE_B + r * 80 + c * 16, src, sz);
        }
    };

    stageg(0, 0);
    CP_COMMIT();

    for (int kb = 0; kb < 24; kb++) {
        __syncthreads();
        if (kb + 1 < 24) stageg(kb + 1, (kb + 1) & 1);
        CP_COMMIT();
        CP_WAIT1();
        __syncthreads();

        const uint32_t sb = smb + (kb & 1) * STAGE_G;
        #pragma unroll
        for (int ks = 0; ks < 2; ks++) {
            #pragma unroll
            for (int sa = 0; sa < 2; sa++) {
                uint32_t af[4][4];
                #pragma unroll
                for (int i = 0; i < 4; i++)
                    ldsm4(af[i], sb + sa * TILE_B +
                          (uint32_t)((wr * 64 + i * 16 + aro) * 80 + ks * 32 + aco));
                #pragma unroll
                for (int sb2 = 0; sb2 < 2 - sa; sb2++) {
                    uint32_t bf[4][2], r4[4];
                    ldsm4(r4, sb + (2 + sb2) * TILE_B +
                          (uint32_t)((wc * 32 + bro) * 80 + ks * 32 + bco));
                    bf[0][0] = r4[0]; bf[0][1] = r4[1];
                    bf[1][0] = r4[2]; bf[1][1] = r4[3];
                    ldsm4(r4, sb + (2 + sb2) * TILE_B +
                          (uint32_t)((wc * 32 + 16 + bro) * 80 + ks * 32 + bco));
                    bf[2][0] = r4[0]; bf[2][1] = r4[1];
                    bf[3][0] = r4[2]; bf[3][1] = r4[3];
                    #pragma unroll
                    for (int i = 0; i < 4; i++)
                        #pragma unroll
                        for (int j = 0; j < 4; j++)
                            mma16816(acc[i][j], af[i][0], af[i][1], af[i][2],
                                     af[i][3], bf[j][0], bf[j][1]);
                }
            }
        }
    }

    // epilogue: scatter q/k/v bf16 splits (q pre-scaled)
    #pragma unroll
    for (int i = 0; i < 4; i++) {
        #pragma unroll
        for (int half = 0; half < 2; half++) {
            int gm = m0 + wr * 64 + i * 16 + gid + half * 8;
            if (gm >= M_TOT) continue;
            int btok = gm / N_, nt = gm % N_;
            #pragma unroll
            for (int j = 0; j < 4; j++) {
                float v0 = acc[i][j][half * 2];
                float v1 = acc[i][j][half * 2 + 1];
                int jg = n0 + wc * 32 + j * 8 + tig * 2;
                int qkv_i = jg / C_;
                int rem = jg % C_;
                int h = rem >> 6, d0 = rem & 63;
                if (qkv_i == 0) { v0 *= SCLOG2E; v1 *= SCLOG2E; }
                __nv_bfloat16* dh = (qkv_i == 0) ? g_qs[0]
                                    : (qkv_i == 1 ? g_ks[0] : g_vs[0]);
                __nv_bfloat16* dl = (qkv_i == 0) ? g_qs[1]
                                    : (qkv_i == 1 ? g_ks[1] : g_vs[1]);
                long base = ((long)(btok * H_ + h) * N_ + nt) * 64 + d0;
                uint32_t hi, lo;
                split_pack(v0, v1, hi, lo);
                *(uint32_t*)&dh[base] = hi;
                *(uint32_t*)&dl[base] = lo;
            }
        }
    }
}

// ======================================================================
// out projection GEMM
// ======================================================================
__global__ void __launch_bounds__(256, 2)
out_gemm(const __nv_bfloat16* __restrict__ A0, const __nv_bfloat16* __restrict__ A1,
         const __nv_bfloat16* __restrict__ B0, const __nv_bfloat16* __restrict__ B1,
         const float* __restrict__ bias, float* __restrict__ out) {
    extern __shared__ __align__(16) char smem[];
    const uint32_t smb = (uint32_t)__cvta_generic_to_shared(smem);
    const int tid = threadIdx.x;
    const int wid = tid >> 5, lane = tid & 31;
    const int gid = lane >> 2, tig = lane & 3;
    const int wr = wid >> 2, wc = wid & 3;
    const int m0 = blockIdx.y * 128;
    const int n0 = blockIdx.x * 128;

    const int lr = lane & 7;
    const int aro = lr + ((lane >> 3) & 1) * 8;
    const int aco = (lane >> 4) * 16;
    const int bro = lr + (lane >> 4) * 8;
    const int bco = ((lane >> 3) & 1) * 16;

    const __nv_bfloat16* Asrc[2] = {A0, A1};
    const __nv_bfloat16* Bsrc[2] = {B0, B1};

    float acc[4][4][4];
    #pragma unroll
    for (int i = 0; i < 4; i++)
        #pragma unroll
        for (int j = 0; j < 4; j++)
            #pragma unroll
            for (int r = 0; r < 4; r++) acc[i][j][r] = 0.f;

    auto stageg = [&](int kb_, int bufi) {
        const int kcol = kb_ * 32;
        const uint32_t sb = smb + bufi * STAGE_G;
        #pragma unroll
        for (int t = 0; t < 8; t++) {
            int idx = tid + t * 256;
            int a = idx >> 9;
            int r = (idx >> 2) & 127, c = idx & 3;
            const __nv_bfloat16* src;
            int sz = 16;
            if (a < 2) {
                src = Asrc[a] + (long)(m0 + r) * C_ + kcol + c * 8;
                if (m0 + r >= M_TOT) sz = 0;
            } else {
                src = Bsrc[a - 2] + (long)(n0 + r) * C_ + kcol + c * 8;
            }
            cpa16(sb + a * TILE_B + r * 80 + c * 16, src, sz);
        }
    };

    stageg(0, 0);
    CP_COMMIT();

    for (int kb = 0; kb < 24; kb++) {
        __syncthreads();
        if (kb + 1 < 24) stageg(kb + 1, (kb + 1) & 1);
        CP_COMMIT();
        CP_WAIT1();
        __syncthreads();

        const uint32_t sb = smb + (kb & 1) * STAGE_G;
        #pragma unroll
        for (int ks = 0; ks < 2; ks++) {
            #pragma unroll
            for (int sa = 0; sa < 2; sa++) {
                uint32_t af[4][4];
                #pragma unroll
                for (int i = 0; i < 4; i++)
                    ldsm4(af[i], sb + sa * TILE_B +
                          (uint32_t)((wr * 64 + i * 16 + aro) * 80 + ks * 32 + aco));
                #pragma unroll
                for (int sb2 = 0; sb2 < 2 - sa; sb2++) {
                    uint32_t bf[4][2], r4[4];
                    ldsm4(r4, sb + (2 + sb2) * TILE_B +
                          (uint32_t)((wc * 32 + bro) * 80 + ks * 32 + bco));
                    bf[0][0] = r4[0]; bf[0][1] = r4[1];
                    bf[1][0] = r4[2]; bf[1][1] = r4[3];
                    ldsm4(r4, sb + (2 + sb2) * TILE_B +
                          (uint32_t)((wc * 32 + 16 + bro) * 80 + ks * 32 + bco));
                    bf[2][0] = r4[0]; bf[2][1] = r4[1];
                    bf[3][0] = r4[2]; bf[3][1] = r4[3];
                    #pragma unroll
                    for (int i = 0; i < 4; i++)
                        #pragma unroll
                        for (int j = 0; j < 4; j++)
                            mma16816(acc[i][j], af[i][0], af[i][1], af[i][2],
                                     af[i][3], bf[j][0], bf[j][1]);
                }
            }
        }
    }

    #pragma unroll
    for (int i = 0; i < 4; i++) {
        #pragma unroll
        for (int half = 0; half < 2; half++) {
            int gm = m0 + wr * 64 + i * 16 + gid + half * 8;
            if (gm >= M_TOT) continue;
            #pragma unroll
            for (int j = 0; j < 4; j++) {
                int jg = n0 + wc * 32 + j * 8 + tig * 2;
                long base = OFF_OUT + (long)gm * C_ + jg;
                *(float2*)&out[base] = make_float2(
                    acc[i][j][half*2]   + bias[jg],
                    acc[i][j][half*2+1] + bias[jg + 1]);
            }
        }
    }
}

// ======================================================================
// mma.sync flash attention (unchanged from R14/R15).
// ======================================================================
#define TILE_A  9216
#define STAGE_A (4 * TILE_A)             // 36864 B per stage
#define QREG_B  (2 * 128 * 144)          // 36864 B (Q hi+lo)
#define ATTN_SMEM3 (QREG_B + 2 * STAGE_A)  // 110592 B

__global__ void __launch_bounds__(256, 2)
attn_mma() {
    extern __shared__ __align__(16) uint32_t asw[];
    const uint32_t smb = (uint32_t)__cvta_generic_to_shared(asw);
    const int tid = threadIdx.x;
    const int wid = tid >> 5, lane = tid & 31;
    const int gid = lane >> 2, tig = lane & 3;
    const int bh = blockIdx.y;
    const int q0g = blockIdx.x * 128;

    const int lr = lane & 7;
    const int aro = lr + ((lane >> 3) & 1) * 8;
    const int aco = (lane >> 4) * 16;
    const int bro = lr + (lane >> 4) * 8;
    const int bco = ((lane >> 3) & 1) * 16;
    const int vro = lr + ((lane >> 3) & 1) * 8;
    const int vco = (lane >> 4) * 16;

    const __nv_bfloat16* Qh = g_qs[0] + (long)bh * N_ * 64;
    const __nv_bfloat16* Ql = g_qs[1] + (long)bh * N_ * 64;
    const __nv_bfloat16* Kh = g_ks[0] + (long)bh * N_ * 64;
    const __nv_bfloat16* Kl = g_ks[1] + (long)bh * N_ * 64;
    const __nv_bfloat16* Vh = g_vs[0] + (long)bh * N_ * 64;
    const __nv_bfloat16* Vl = g_vs[1] + (long)bh * N_ * 64;

    {
        __nv_bfloat16* Q0 = (__nv_bfloat16*)asw;
        __nv_bfloat16* Q1 = (__nv_bfloat16*)((char*)asw + 18432);
        for (int idx = tid; idx < 128 * 8; idx += 256) {
            int r = idx >> 3, c = idx & 7;
            int qi = q0g + r;
            uint4 vh = make_uint4(0, 0, 0, 0), vl = vh;
            if (qi < N_) {
                vh = *(const uint4*)(Qh + (long)qi * 64 + c * 8);
                vl = *(const uint4*)(Ql + (long)qi * 64 + c * 8);
            }
            *(uint4*)(Q0 + r * 72 + c * 8) = vh;
            *(uint4*)(Q1 + r * 72 + c * 8) = vl;
        }
    }

    float accD[8][4];
    #pragma unroll
    for (int dt = 0; dt < 8; dt++)
        #pragma unroll
        for (int r = 0; r < 4; r++) accD[dt][r] = 0.f;
    float m2[2] = {-INFINITY, -INFINITY};
    float l2[2] = {0.f, 0.f};

    const int rlo = q0g + wid * 16;
    const bool w_dead = (rlo >= N_);
    bool wq_uni = false; int wqb = -2;
    int wblk_lo = 5, wblk_hi = -5;
    if (!w_dead) {
        int rhi = min(rlo + 15, N_ - 1);
        int blo = (max(rlo, 1) - 1) >> 8;
        int bhi = (rhi >= 1) ? ((rhi - 1) >> 8) : -1;
        wblk_lo = blo; wblk_hi = bhi;
        if (rlo >= 1 && blo == bhi) { wq_uni = true; wqb = blo; }
    }
    const int row0g = rlo + gid, row1g = rlo + gid + 8;
    const int qb0 = (row0g >= 1 && row0g < N_) ? ((row0g - 1) >> 8) : -1;
    const int qb1 = (row1g >= 1 && row1g < N_) ? ((row1g - 1) >> 8) : -1;

    auto stagea = [&](int kt_, int bufi) {
        const int k0 = kt_ * 64;
        const uint32_t sb = smb + QREG_B + bufi * STAGE_A;
        const __nv_bfloat16* srcs[4] = {Kh, Kl, Vh, Vl};
        #pragma unroll
        for (int t = 0; t < 8; t++) {
            int idx = tid + t * 256;
            int a = idx >> 9, r = (idx >> 3) & 63, c = idx & 7;
            int kj = k0 + r;
            const __nv_bfloat16* src = srcs[a] + (long)kj * 64 + c * 8;
            cpa16(sb + a * TILE_A + r * 144 + c * 16, src, (kj < N_) ? 16 : 0);
        }
    };

    stagea(0, 0);
    CP_COMMIT();
    __syncthreads();

    for (int kt = 0; kt < 17; kt++) {
        const int k0g = kt * 64;
        __syncthreads();
        if (kt + 1 < 17) stagea(kt + 1, (kt + 1) & 1);
        CP_COMMIT();
        CP_WAIT1();
        __syncthreads();

        bool skip = w_dead;
        bool need_mask = false;
        if (!skip) {
            int klo = max(k0g, 1), khi = min(k0g + 63, N_ - 1);
            int kbl = (klo - 1) >> 8, kbh = (khi - 1) >> 8;
            if (wq_uni && k0g >= 1 && kbl == kbh && kbl == wqb) skip = true;
            else need_mask = (k0g + 63 >= N_) ||
                             (kbl <= wblk_hi && kbh >= wblk_lo);
        }
        if (skip) continue;

        const uint32_t sb = smb + QREG_B + (kt & 1) * STAGE_A;

        float sp[8][4];
        #pragma unroll
        for (int nt = 0; nt < 8; nt++)
            #pragma unroll
            for (int r = 0; r < 4; r++) sp[nt][r] = 0.f;

        #pragma unroll
        for (int ks = 0; ks < 4; ks++) {
            uint32_t qh4[4], ql4[4];
            uint32_t qoff = (uint32_t)((wid * 16 + aro) * 144 + ks * 32 + aco);
            ldsm4(qh4, smb + qoff);
            ldsm4(ql4, smb + 18432 + qoff);
            #pragma unroll
            for (int ntp = 0; ntp < 4; ntp++) {
                uint32_t rowb = (uint32_t)((ntp * 16 + bro) * 144 + ks * 32 + bco);
                uint32_t h4[4], l4[4];
                ldsm4(h4, sb + rowb);
                ldsm4(l4, sb + TILE_A + rowb);
                mma16816(sp[2*ntp], qh4[0], qh4[1], qh4[2], qh4[3], h4[0], h4[1]);
                mma16816(sp[2*ntp], ql4[0], ql4[1], ql4[2], ql4[3], h4[0], h4[1]);
                mma16816(sp[2*ntp], qh4[0], qh4[1], qh4[2], qh4[3], l4[0], l4[1]);
                mma16816(sp[2*ntp+1], qh4[0], qh4[1], qh4[2], qh4[3], h4[2], h4[3]);
                mma16816(sp[2*ntp+1], ql4[0], ql4[1], ql4[2], ql4[3], h4[2], h4[3]);
                mma16816(sp[2*ntp+1], qh4[0], qh4[1], qh4[2], qh4[3], l4[2], l4[3]);
            }
        }

        if (need_mask) {
            #pragma unroll
            for (int nt = 0; nt < 8; nt++) {
                #pragma unroll
                for (int c = 0; c < 4; c++) {
                    int qb = (c >= 2) ? qb1 : qb0;
                    int key = k0g + nt * 8 + 2 * tig + (c & 1);
                    bool bad = (key >= N_) ||
                               (qb >= 0 && key >= 1 && ((key - 1) >> 8) == qb);
                    if (bad) sp[nt][c] = -INFINITY;
                }
            }
        }

        #pragma unroll
        for (int half = 0; half < 2; half++) {
            float mx = -INFINITY;
            #pragma unroll
            for (int nt = 0; nt < 8; nt++)
                mx = fmaxf(mx, fmaxf(sp[nt][half*2], sp[nt][half*2+1]));
            mx = fmaxf(mx, __shfl_xor_sync(0xffffffffu, mx, 1));
            mx = fmaxf(mx, __shfl_xor_sync(0xffffffffu, mx, 2));
            float mnew = fmaxf(m2[half], mx);
            float corr = exp2f(m2[half] - mnew);
            m2[half] = mnew;
            float rs = 0.f;
            #pragma unroll
            for (int nt = 0; nt < 8; nt++) {
                float p0 = exp2f(sp[nt][half*2]   - mnew);
                float p1 = exp2f(sp[nt][half*2+1] - mnew);
                sp[nt][half*2] = p0; sp[nt][half*2+1] = p1;
                rs += p0 + p1;
            }
            rs += __shfl_xor_sync(0xffffffffu, rs, 1);
            rs += __shfl_xor_sync(0xffffffffu, rs, 2);
            l2[half] = l2[half] * corr + rs;
            #pragma unroll
            for (int dt = 0; dt < 8; dt++) {
                accD[dt][half*2]   *= corr;
                accD[dt][half*2+1] *= corr;
            }
        }

        #pragma unroll
        for (int ks = 0; ks < 4; ks++) {
            uint32_t p0[4], p1[4];
            split_pack(sp[2*ks][0],   sp[2*ks][1],   p0[0], p1[0]);
            split_pack(sp[2*ks][2],   sp[2*ks][3],   p0[1], p1[1]);
            split_pack(sp[2*ks+1][0], sp[2*ks+1][1], p0[2], p1[2]);
            split_pack(sp[2*ks+1][2], sp[2*ks+1][3], p0[3], p1[3]);
            #pragma unroll
            for (int dtp = 0; dtp < 4; dtp++) {
                uint32_t rowb = (uint32_t)((ks * 16 + vro) * 144 + dtp * 32 + vco);
                uint32_t h4[4], l4[4];
                ldsm4t(h4, sb + 2 * TILE_A + rowb);
                ldsm4t(l4, sb + 3 * TILE_A + rowb);
                mma16816(accD[2*dtp], p0[0], p0[1], p0[2], p0[3], h4[0], h4[1]);
                mma16816(accD[2*dtp], p1[0], p1[1], p1[2], p1[3], h4[0], h4[1]);
                mma16816(accD[2*dtp], p0[0], p0[1], p0[2], p0[3], l4[0], l4[1]);
                mma16816(accD[2*dtp+1], p0[0], p0[1], p0[2], p0[3], h4[2], h4[3]);
                mma16816(accD[2*dtp+1], p1[0], p1[1], p1[2], p1[3], h4[2], h4[3]);
                mma16816(accD[2*dtp+1], p0[0], p0[1], p0[2], p0[3], l4[2], l4[3]);
            }
        }
    }

    const int b = bh / H_, h = bh % H_;
    #pragma unroll
    for (int half = 0; half < 2; half++) {
        int row = rlo + gid + half * 8;
        if (row < N_) {
            float inv = 1.f / l2[half];
            #pragma unroll
            for (int dt = 0; dt < 8; dt++) {
                int d = dt * 8 + 2 * tig;
                long base = ((long)b * N_ + row) * C_ + h * 64 + d;
                uint32_t hi, lo;
                split_pack(accD[dt][half*2] * inv, accD[dt][half*2+1] * inv, hi, lo);
                *(uint32_t*)&g_cs[0][base] = hi;
                *(uint32_t*)&g_cs[1][base] = lo;
            }
        }
    }
}

// ======================================================================
// cls softmax over precomputed scores (fp64). One CTA per (b,h).
// ======================================================================
__global__ void __launch_bounds__(1024)
cls_soft_kernel() {
    __shared__ double s[N_];
    __shared__ double red[32];
    const int bh = blockIdx.x;
    const int tid = threadIdx.x;
    const int wid = tid >> 5, lane = tid & 31;

    for (int j = tid; j < N_; j += 1024) s[j] = g_cls_s[bh][j];
    __syncthreads();

    double lm = -1e300;
    for (int j = tid; j < N_; j += 1024) lm = fmax(lm, s[j]);
    #pragma unroll
    for (int o = 16; o >= 1; o >>= 1)
        lm = fmax(lm, __shfl_xor_sync(0xffffffffu, lm, o));
    if (lane == 0) red[wid] = lm;
    __syncthreads();
    if (wid == 0) {
        double t = red[lane];
        #pragma unroll
        for (int o = 16; o >= 1; o >>= 1)
            t = fmax(t, __shfl_xor_sync(0xffffffffu, t, o));
        if (lane == 0) red[0] = t;
    }
    __syncthreads();
    const double m = red[0];
    __syncthreads();

    double ls = 0.0;
    for (int j = tid; j < N_; j += 1024) {
        double e = exp(s[j] - m);
        s[j] = e;
        ls += e;
    }
    #pragma unroll
    for (int o = 16; o >= 1; o >>= 1)
        ls += __shfl_xor_sync(0xffffffffu, ls, o);
    if (lane == 0) red[wid] = ls;
    __syncthreads();
    if (wid == 0) {
        double t = red[lane];
        #pragma unroll
        for (int o = 16; o >= 1; o >>= 1)
            t += __shfl_xor_sync(0xffffffffu, t, o);
        if (lane == 0) red[0] = t;
    }
    __syncthreads();
    const double inv = 1.0 / red[0];

    for (int j = tid; j < N_ - 1; j += 1024)
        g_cls_ph[bh][j] = s[j + 1] * inv;
}

// ======================================================================
// head-mean reduce (fp64, h-ascending). One CTA per batch.
// ======================================================================
__global__ void cls_reduce_kernel(float* __restrict__ out) {
    const int b = blockIdx.x, tid = threadIdx.x;
    for (int j = tid; j < N_ - 1; j += 256) {
        double a = 0.0;
        #pragma unroll
        for (int h = 0; h < H_; h++)
            a += g_cls_ph[b * H_ + h][j] * (1.0 / 12.0);
        g_clsd[b * (N_ - 1) + j] = a;
        out[OFF_CLS + (long)b * (N_ - 1) + j] = (float)a;
    }
}

// ======================================================================
// dual bitonic top-k (103 of 1024) on fp64 keys, jax tie-break.
// ======================================================================
__global__ void sort_kernel(float* __restrict__ out) {
    __shared__ double v[1024];
    __shared__ int ix[1024];
    const int b = blockIdx.x, tid = threadIdx.x;

    for (int pass = 0; pass < 2; pass++) {
        __syncthreads();
        for (int i = tid; i < 1024; i += 512) {
            v[i] = g_clsd[b * 1024 + i];
            ix[i] = i;
        }
        __syncthreads();
        const bool desc = (pass == 0);
        for (int k = 2; k <= 1024; k <<= 1) {
            for (int j = k >> 1; j > 0; j >>= 1) {
                for (int i = tid; i < 1024; i += 512) {
                    int p = i ^ j;
                    if (p > i) {
                        double va = v[i], vb = v[p];
                        int ia = ix[i], ib = ix[p];
                        bool ab = desc ? (va > vb || (va == vb && ia < ib))
                                       : (va < vb || (va == vb && ia < ib));
                        bool up = ((i & k) == 0);
                        if (up ? !ab : ab) {
                            v[i] = vb; v[p] = va;
                            ix[i] = ib; ix[p] = ia;
                        }
                    }
                }
                __syncthreads();
            }
        }
        const long offIdx = desc ? OFF_ENH_IDX : OFF_FUSE_IDX;
        const long offBrd = desc ? OFF_ENH_INDEX : OFF_FUSE_INDEX;
        for (int t = tid; t < TOPT; t += 512)
            out[offIdx + (long)b * TOPT + t] = (float)ix[t];
        for (int e = tid; e < TOPT * C_; e += 512) {
            int t = e / C_;
            out[offBrd + ((long)b * TOPT + t) * C_ + (e % C_)] = (float)ix[t];
        }
    }
}

// ======================================================================
// Launch
// ======================================================================
extern "C" void kernel_launch(void* const* d_in, const int* in_sizes, int n_in,
                              void* d_out, int out_size) {
    const float* x     = (const float*)d_in[0];
    const float* w_qkv = (const float*)d_in[1];
    const float* w_out = (const float*)d_in[2];
    const float* b_out = (const float*)d_in[3];
    float* out = (float*)d_out;

    cudaFuncSetAttribute(fused_qkv_cls, cudaFuncAttributeMaxDynamicSharedMemorySize,
                         MMA_SMEM);
    cudaFuncSetAttribute(out_gemm, cudaFuncAttributeMaxDynamicSharedMemorySize,
                         MMA_SMEM);
    cudaFuncSetAttribute(attn_mma, cudaFuncAttributeMaxDynamicSharedMemorySize,
                         ATTN_SMEM3);

    __nv_bfloat16 *xs0, *xs1, *ws0, *ws1, *wo0, *wo1, *cs0, *cs1;
    cudaGetSymbolAddress((void**)&xs0, g_xs); xs1 = xs0 + (long)M_TOT*C_;
    cudaGetSymbolAddress((void**)&ws0, g_ws); ws1 = ws0 + (long)3*C_*C_;
    cudaGetSymbolAddress((void**)&wo0, g_wo); wo1 = wo0 + (long)C_*C_;
    cudaGetSymbolAddress((void**)&cs0, g_cs); cs1 = cs0 + (long)M_TOT*C_;

    // cls u-vectors (48 tiny blocks, own launch -> no occupancy tax)
    cls_u_kernel<<<B_ * H_, 256>>>(x, w_qkv);

    // lean splits
    split2<<<(M_TOT*C_ + 255)/256, 256>>>(x, xs0, xs1, M_TOT*C_);
    split2<<<(3*C_*C_ + 255)/256, 256>>>(w_qkv, ws0, ws1, 3*C_*C_);
    split2<<<(C_*C_ + 255)/256, 256>>>(w_out, wo0, wo1, C_*C_);

    // fused: cls phase-3 chunks (0..191) + QKV GEMM (192..785)
    fused_qkv_cls<<<CLS_BLOCKS + QKV_BLOCKS, 256, MMA_SMEM>>>(
        xs0, xs1, ws0, ws1, x);

    // attention -> ctx bf16 splits directly
    attn_mma<<<dim3((N_ + 127)/128, B_ * H_), 256, ATTN_SMEM3>>>();

    // OUT: [4100,768] = ctx @ w_out^T + bias
    out_gemm<<<dim3(C_/128, (M_TOT + 127)/128), 256, MMA_SMEM>>>(
        cs0, cs1, wo0, wo1, b_out, out);

    // cls tail: fp64 softmax over precomputed scores, mean, top-k
    cls_soft_kernel<<<B_ * H_, 1024>>>();
    cls_reduce_kernel<<<B_, 256>>>(out);
    sort_kernel<<<B_, 512>>>(out);
}

// round 17
// speedup vs baseline: 1.0610x; 1.0607x over previous
#include <cuda_runtime.h>
#include <cuda_bf16.h>
#include <math.h>
#include <cstdint>

// ---------------- Problem constants ----------------
#define B_ 4
#define N_ 1025
#define C_ 768
#define H_ 12
#define D_ 64
#define TOPT 103
#define SCALEF 0.125f            // 64^-0.5
#define SCLOG2E (0.125f * 1.4426950408889634f)   // fold scale * log2(e) into Q

#define M_TOT (B_ * N_)          // 4100

// Output layout (float32, reference tuple flattened & concatenated):
#define OFF_OUT        0L
#define OFF_ENH_INDEX  3148800L
#define OFF_ENH_IDX    3465216L
#define OFF_FUSE_INDEX 3465628L
#define OFF_FUSE_IDX   3782044L
#define OFF_CLS        3782456L

// ---------------- Scratch (no allocation allowed) ----------------
__device__ double g_clsd[B_*(N_-1)];
__device__ double g_cls_ph[B_*H_][N_-1];
__device__ double g_cls_s[B_*H_][N_];     // raw cls scores (fp64-accurate)
__device__ float  g_u[2][B_*H_][C_];      // (unused placeholder kept for layout)

// bf16 2-way splits
__device__ __nv_bfloat16 g_xs[2][M_TOT*C_];
__device__ __nv_bfloat16 g_ws[2][3*C_*C_];     // w_qkv [2304,768]
__device__ __nv_bfloat16 g_wo[2][C_*C_];       // w_out [768,768]
__device__ __nv_bfloat16 g_cs[2][M_TOT*C_];    // ctx splits (written by attn)
// q/k/v as bf16 splits, [b,h,n,d]; q pre-scaled by SCALE*log2e
__device__ __nv_bfloat16 g_qs[2][B_*H_*N_*D_];
__device__ __nv_bfloat16 g_ks[2][B_*H_*N_*D_];
__device__ __nv_bfloat16 g_vs[2][B_*H_*N_*D_];

// ================= helpers =================
__device__ __forceinline__ void ldsm4(uint32_t* r, uint32_t addr) {
    asm volatile("ldmatrix.sync.aligned.m8n8.x4.shared.b16 {%0,%1,%2,%3}, [%4];"
        : "=r"(r[0]), "=r"(r[1]), "=r"(r[2]), "=r"(r[3]) : "r"(addr));
}
__device__ __forceinline__ void ldsm4t(uint32_t* r, uint32_t addr) {
    asm volatile("ldmatrix.sync.aligned.m8n8.x4.trans.shared.b16 {%0,%1,%2,%3}, [%4];"
        : "=r"(r[0]), "=r"(r[1]), "=r"(r[2]), "=r"(r[3]) : "r"(addr));
}
__device__ __forceinline__ void mma16816(float c[4], uint32_t a0, uint32_t a1,
                                         uint32_t a2, uint32_t a3,
                                         uint32_t b0, uint32_t b1) {
    asm volatile(
        "mma.sync.aligned.m16n8k16.row.col.f32.bf16.bf16.f32 "
        "{%0,%1,%2,%3}, {%4,%5,%6,%7}, {%8,%9}, {%0,%1,%2,%3};"
        : "+f"(c[0]), "+f"(c[1]), "+f"(c[2]), "+f"(c[3])
        : "r"(a0), "r"(a1), "r"(a2), "r"(a3), "r"(b0), "r"(b1));
}
__device__ __forceinline__ void cpa16(uint32_t dst, const void* src, int sz) {
    asm volatile("cp.async.cg.shared.global [%0], [%1], 16, %2;"
        :: "r"(dst), "l"(src), "r"(sz));
}
#define CP_COMMIT() asm volatile("cp.async.commit_group;" ::: "memory")
#define CP_WAIT1()  asm volatile("cp.async.wait_group 1;" ::: "memory")
// fp32 pair -> bf16x2 hi split + bf16x2 residual split (RN rounding)
__device__ __forceinline__ void split_pack(float x, float y,
                                           uint32_t& hi, uint32_t& lo) {
    asm("cvt.rn.bf16x2.f32 %0, %1, %2;" : "=r"(hi) : "f"(y), "f"(x));
    float fx = __uint_as_float(hi << 16);
    float fy = __uint_as_float(hi & 0xFFFF0000u);
    asm("cvt.rn.bf16x2.f32 %0, %1, %2;" : "=r"(lo) : "f"(y - fy), "f"(x - fx));
}

// ======================================================================
// Split kernel: fp32 -> 2 bf16 splits (residual ~2^-16)
// ======================================================================
__global__ void split2(const float* __restrict__ src,
                       __nv_bfloat16* __restrict__ d0,
                       __nv_bfloat16* __restrict__ d1, int n) {
    int i = blockIdx.x * blockDim.x + threadIdx.x;
    if (i < n) {
        float x = src[i];
        __nv_bfloat16 b0 = __float2bfloat16(x);
        d0[i] = b0;
        d1[i] = __float2bfloat16(x - __bfloat162float(b0));
    }
}

// ======================================================================
// GEMM constants
// ======================================================================
#define TILE_B  (128 * 80)               // 10240 B per split tile (80B rows)
#define STAGE_G (4 * TILE_B)             // 40960 B per stage
#define MMA_SMEM (2 * STAGE_G)           // 81920 B
#define CLS_BLOCKS 192                   // 48 bh x 4 j-chunks
#define QKV_BLOCKS 594                   // 18 x 33

// ---------------- cls score chunk (runs inside fused launch) ----------
// s_j = 0.125*(W_k,h^T (W_q,h x_{b,0})) . x_{b,j} for a j-chunk.
// fp64 phases 1-2 + Kahan-compensated fp32 phase 3 (identical per-j math
// and order to R14); phase 3 uses 2-way j-ILP to hide L2 latency.
__device__ void cls_chunk_body(const float* __restrict__ x,
                               const float* __restrict__ w, char* smem) {
    double* q0s = (double*)smem;               // 64 doubles
    float* uhi = (float*)(smem + 512);         // 768 floats
    float* ulo = (float*)(smem + 512 + 3072);  // 768 floats
    const int id = blockIdx.x;
    const int bh = id >> 2, chunk = id & 3;
    const int b = bh / H_, h = bh % H_;
    const int tid = threadIdx.x;
    const int wid = tid >> 5, lane = tid & 31;

    const float* xb = x + (long)b * N_ * C_;
    const float* wq = w + (long)(h * 64) * C_;
    const float* wk = w + (long)(C_ + h * 64) * C_;

    // phase 1: q0[d] fp64 (warp per d)
    for (int d = wid; d < 64; d += 8) {
        double a = 0.0;
        for (int c = lane; c < C_; c += 32)
            a += (double)xb[c] * (double)wq[(long)d * C_ + c];
        #pragma unroll
        for (int o = 16; o >= 1; o >>= 1)
            a += __shfl_xor_sync(0xffffffffu, a, o);
        if (lane == 0) q0s[d] = a;
    }
    __syncthreads();

    // phase 2: u[c] = 0.125 * sum_d q0[d]*wk[d][c] (fp64), hi/lo fp32
    for (int c = tid; c < C_; c += 256) {
        double a = 0.0;
        #pragma unroll 8
        for (int d = 0; d < 64; d++)
            a += q0s[d] * (double)wk[(long)d * C_ + c];
        a *= 0.125;
        float hi = (float)a;
        uhi[c] = hi;
        ulo[c] = (float)(a - (double)hi);
    }
    __syncthreads();

    // phase 3: s[j], warp handles (j, j+1) concurrently (independent Kahan
    // states, identical per-j op sequence -> bit-identical results).
    const int jlo = chunk * 257;
    const int jhi = min(jlo + 257, N_);
    for (int j = jlo + 2 * wid; j < jhi; j += 16) {
        const int jB = j + 1;
        const bool hasB = (jB < jhi);
        const float* xrA = xb + (long)j * C_;
        const float* xrB = xb + (long)(hasB ? jB : j) * C_;
        float sumA = 0.f, compA = 0.f, errA = 0.f;
        float sumB = 0.f, compB = 0.f, errB = 0.f;
        #pragma unroll 2
        for (int c = lane * 4; c < C_; c += 128) {
            float4 xvA = *(const float4*)&xrA[c];
            float4 xvB = *(const float4*)&xrB[c];
            float4 uh = *(const float4*)&uhi[c];
            float4 ul = *(const float4*)&ulo[c];
            #pragma unroll
            for (int e4 = 0; e4 < 4; e4++) {
                float he = (&uh.x)[e4], le = (&ul.x)[e4];
                {   // lane A
                    float xe = (&xvA.x)[e4];
                    float p = he * xe;
                    errA = fmaf(he, xe, -p) + errA;
                    errA = fmaf(le, xe, errA);
                    float y = p - compA;
                    float t = sumA + y;
                    compA = (t - sumA) - y;
                    sumA = t;
                }
                {   // lane B (independent chain)
                    float xe = (&xvB.x)[e4];
                    float p = he * xe;
                    errB = fmaf(he, xe, -p) + errB;
                    errB = fmaf(le, xe, errB);
                    float y = p - compB;
                    float t = sumB + y;
                    compB = (t - sumB) - y;
                    sumB = t;
                }
            }
        }
        double totA = ((double)sumA - (double)compA) + (double)errA;
        double totB = ((double)sumB - (double)compB) + (double)errB;
        #pragma unroll
        for (int o = 16; o >= 1; o >>= 1) {
            totA += __shfl_xor_sync(0xffffffffu, totA, o);
            totB += __shfl_xor_sync(0xffffffffu, totB, o);
        }
        if (lane == 0) {
            g_cls_s[bh][j] = totA;
            if (hasB) g_cls_s[bh][jB] = totB;
        }
    }
}

// ======================================================================
// Fused: blocks [0,192) = cls score chunks; blocks [192,786) = QKV GEMM.
// ======================================================================
__global__ void __launch_bounds__(256, 2)
fused_qkv_cls(const __nv_bfloat16* __restrict__ A0,
              const __nv_bfloat16* __restrict__ A1,
              const __nv_bfloat16* __restrict__ B0,
              const __nv_bfloat16* __restrict__ B1,
              const float* __restrict__ x, const float* __restrict__ w) {
    extern __shared__ __align__(16) char smem[];
    if (blockIdx.x < CLS_BLOCKS) {
        cls_chunk_body(x, w, smem);
        return;
    }
    const uint32_t smb = (uint32_t)__cvta_generic_to_shared(smem);
    const int bidx = blockIdx.x - CLS_BLOCKS;
    const int m0 = (bidx / 18) * 128;
    const int n0 = (bidx % 18) * 128;
    const int tid = threadIdx.x;
    const int wid = tid >> 5, lane = tid & 31;
    const int gid = lane >> 2, tig = lane & 3;
    const int wr = wid >> 2, wc = wid & 3;

    const int lr = lane & 7;
    const int aro = lr + ((lane >> 3) & 1) * 8;
    const int aco = (lane >> 4) * 16;
    const int bro = lr + (lane >> 4) * 8;
    const int bco = ((lane >> 3) & 1) * 16;

    const __nv_bfloat16* Asrc[2] = {A0, A1};
    const __nv_bfloat16* Bsrc[2] = {B0, B1};

    float acc[4][4][4];
    #pragma unroll
    for (int i = 0; i < 4; i++)
        #pragma unroll
        for (int j = 0; j < 4; j++)
            #pragma unroll
            for (int r = 0; r < 4; r++) acc[i][j][r] = 0.f;

    auto stageg = [&](int kb_, int bufi) {
        const int kcol = kb_ * 32;
        const uint32_t sb = smb + bufi * STAGE_G;
        #pragma unroll
        for (int t = 0; t < 8; t++) {
            int idx = tid + t * 256;
            int a = idx >> 9;
            int r = (idx >> 2) & 127, c = idx & 3;
            const __nv_bfloat16* src;
            int sz = 16;
            if (a < 2) {
                src = Asrc[a] + (long)(m0 + r) * C_ + kcol + c * 8;
                if (m0 + r >= M_TOT) sz = 0;
            } else {
                src = Bsrc[a - 2] + (long)(n0 + r) * C_ + kcol + c * 8;
            }
            cpa16(sb + a * TILE_B + r * 80 + c * 16, src, sz);
        }
    };

    stageg(0, 0);
    CP_COMMIT();

    for (int kb = 0; kb < 24; kb++) {
        __syncthreads();
        if (kb + 1 < 24) stageg(kb + 1, (kb + 1) & 1);
        CP_COMMIT();
        CP_WAIT1();
        __syncthreads();

        const uint32_t sb = smb + (kb & 1) * STAGE_G;
        #pragma unroll
        for (int ks = 0; ks < 2; ks++) {
            #pragma unroll
            for (int sa = 0; sa < 2; sa++) {
                uint32_t af[4][4];
                #pragma unroll
                for (int i = 0; i < 4; i++)
                    ldsm4(af[i], sb + sa * TILE_B +
                          (uint32_t)((wr * 64 + i * 16 + aro) * 80 + ks * 32 + aco));
                #pragma unroll
                for (int sb2 = 0; sb2 < 2 - sa; sb2++) {
                    uint32_t bf[4][2], r4[4];
                    ldsm4(r4, sb + (2 + sb2) * TILE_B +
                          (uint32_t)((wc * 32 + bro) * 80 + ks * 32 + bco));
                    bf[0][0] = r4[0]; bf[0][1] = r4[1];
                    bf[1][0] = r4[2]; bf[1][1] = r4[3];
                    ldsm4(r4, sb + (2 + sb2) * TILE_B +
                          (uint32_t)((wc * 32 + 16 + bro) * 80 + ks * 32 + bco));
                    bf[2][0] = r4[0]; bf[2][1] = r4[1];
                    bf[3][0] = r4[2]; bf[3][1] = r4[3];
                    #pragma unroll
                    for (int i = 0; i < 4; i++)
                        #pragma unroll
                        for (int j = 0; j < 4; j++)
                            mma16816(acc[i][j], af[i][0], af[i][1], af[i][2],
                                     af[i][3], bf[j][0], bf[j][1]);
                }
            }
        }
    }

    // epilogue: scatter q/k/v bf16 splits (q pre-scaled)
    #pragma unroll
    for (int i = 0; i < 4; i++) {
        #pragma unroll
        for (int half = 0; half < 2; half++) {
            int gm = m0 + wr * 64 + i * 16 + gid + half * 8;
            if (gm >= M_TOT) continue;
            int btok = gm / N_, nt = gm % N_;
            #pragma unroll
            for (int j = 0; j < 4; j++) {
                float v0 = acc[i][j][half * 2];
                float v1 = acc[i][j][half * 2 + 1];
                int jg = n0 + wc * 32 + j * 8 + tig * 2;
                int qkv_i = jg / C_;
                int rem = jg % C_;
                int h = rem >> 6, d0 = rem & 63;
                if (qkv_i == 0) { v0 *= SCLOG2E; v1 *= SCLOG2E; }
                __nv_bfloat16* dh = (qkv_i == 0) ? g_qs[0]
                                    : (qkv_i == 1 ? g_ks[0] : g_vs[0]);
                __nv_bfloat16* dl = (qkv_i == 0) ? g_qs[1]
                                    : (qkv_i == 1 ? g_ks[1] : g_vs[1]);
                long base = ((long)(btok * H_ + h) * N_ + nt) * 64 + d0;
                uint32_t hi, lo;
                split_pack(v0, v1, hi, lo);
                *(uint32_t*)&dh[base] = hi;
                *(uint32_t*)&dl[base] = lo;
            }
        }
    }
}

// ======================================================================
// out projection GEMM
// ======================================================================
__global__ void __launch_bounds__(256, 2)
out_gemm(const __nv_bfloat16* __restrict__ A0, const __nv_bfloat16* __restrict__ A1,
         const __nv_bfloat16* __restrict__ B0, const __nv_bfloat16* __restrict__ B1,
         const float* __restrict__ bias, float* __restrict__ out) {
    extern __shared__ __align__(16) char smem[];
    const uint32_t smb = (uint32_t)__cvta_generic_to_shared(smem);
    const int tid = threadIdx.x;
    const int wid = tid >> 5, lane = tid & 31;
    const int gid = lane >> 2, tig = lane & 3;
    const int wr = wid >> 2, wc = wid & 3;
    const int m0 = blockIdx.y * 128;
    const int n0 = blockIdx.x * 128;

    const int lr = lane & 7;
    const int aro = lr + ((lane >> 3) & 1) * 8;
    const int aco = (lane >> 4) * 16;
    const int bro = lr + (lane >> 4) * 8;
    const int bco = ((lane >> 3) & 1) * 16;

    const __nv_bfloat16* Asrc[2] = {A0, A1};
    const __nv_bfloat16* Bsrc[2] = {B0, B1};

    float acc[4][4][4];
    #pragma unroll
    for (int i = 0; i < 4; i++)
        #pragma unroll
        for (int j = 0; j < 4; j++)
            #pragma unroll
            for (int r = 0; r < 4; r++) acc[i][j][r] = 0.f;

    auto stageg = [&](int kb_, int bufi) {
        const int kcol = kb_ * 32;
        const uint32_t sb = smb + bufi * STAGE_G;
        #pragma unroll
        for (int t = 0; t < 8; t++) {
            int idx = tid + t * 256;
            int a = idx >> 9;
            int r = (idx >> 2) & 127, c = idx & 3;
            const __nv_bfloat16* src;
            int sz = 16;
            if (a < 2) {
                src = Asrc[a] + (long)(m0 + r) * C_ + kcol + c * 8;
                if (m0 + r >= M_TOT) sz = 0;
            } else {
                src = Bsrc[a - 2] + (long)(n0 + r) * C_ + kcol + c * 8;
            }
            cpa16(sb + a * TILE_B + r * 80 + c * 16, src, sz);
        }
    };

    stageg(0, 0);
    CP_COMMIT();

    for (int kb = 0; kb < 24; kb++) {
        __syncthreads();
        if (kb + 1 < 24) stageg(kb + 1, (kb + 1) & 1);
        CP_COMMIT();
        CP_WAIT1();
        __syncthreads();

        const uint32_t sb = smb + (kb & 1) * STAGE_G;
        #pragma unroll
        for (int ks = 0; ks < 2; ks++) {
            #pragma unroll
            for (int sa = 0; sa < 2; sa++) {
                uint32_t af[4][4];
                #pragma unroll
                for (int i = 0; i < 4; i++)
                    ldsm4(af[i], sb + sa * TILE_B +
                          (uint32_t)((wr * 64 + i * 16 + aro) * 80 + ks * 32 + aco));
                #pragma unroll
                for (int sb2 = 0; sb2 < 2 - sa; sb2++) {
                    uint32_t bf[4][2], r4[4];
                    ldsm4(r4, sb + (2 + sb2) * TILE_B +
                          (uint32_t)((wc * 32 + bro) * 80 + ks * 32 + bco));
                    bf[0][0] = r4[0]; bf[0][1] = r4[1];
                    bf[1][0] = r4[2]; bf[1][1] = r4[3];
                    ldsm4(r4, sb + (2 + sb2) * TILE_B +
                          (uint32_t)((wc * 32 + 16 + bro) * 80 + ks * 32 + bco));
                    bf[2][0] = r4[0]; bf[2][1] = r4[1];
                    bf[3][0] = r4[2]; bf[3][1] = r4[3];
                    #pragma unroll
                    for (int i = 0; i < 4; i++)
                        #pragma unroll
                        for (int j = 0; j < 4; j++)
                            mma16816(acc[i][j], af[i][0], af[i][1], af[i][2],
                                     af[i][3], bf[j][0], bf[j][1]);
                }
            }
        }
    }

    #pragma unroll
    for (int i = 0; i < 4; i++) {
        #pragma unroll
        for (int half = 0; half < 2; half++) {
            int gm = m0 + wr * 64 + i * 16 + gid + half * 8;
            if (gm >= M_TOT) continue;
            #pragma unroll
            for (int j = 0; j < 4; j++) {
                int jg = n0 + wc * 32 + j * 8 + tig * 2;
                long base = OFF_OUT + (long)gm * C_ + jg;
                *(float2*)&out[base] = make_float2(
                    acc[i][j][half*2]   + bias[jg],
                    acc[i][j][half*2+1] + bias[jg + 1]);
            }
        }
    }
}

// ======================================================================
// mma.sync flash attention (unchanged from R14).
// ======================================================================
#define TILE_A  9216
#define STAGE_A (4 * TILE_A)             // 36864 B per stage
#define QREG_B  (2 * 128 * 144)          // 36864 B (Q hi+lo)
#define ATTN_SMEM3 (QREG_B + 2 * STAGE_A)  // 110592 B

__global__ void __launch_bounds__(256, 2)
attn_mma() {
    extern __shared__ __align__(16) uint32_t asw[];
    const uint32_t smb = (uint32_t)__cvta_generic_to_shared(asw);
    const int tid = threadIdx.x;
    const int wid = tid >> 5, lane = tid & 31;
    const int gid = lane >> 2, tig = lane & 3;
    const int bh = blockIdx.y;
    const int q0g = blockIdx.x * 128;

    const int lr = lane & 7;
    const int aro = lr + ((lane >> 3) & 1) * 8;
    const int aco = (lane >> 4) * 16;
    const int bro = lr + (lane >> 4) * 8;
    const int bco = ((lane >> 3) & 1) * 16;
    const int vro = lr + ((lane >> 3) & 1) * 8;
    const int vco = (lane >> 4) * 16;

    const __nv_bfloat16* Qh = g_qs[0] + (long)bh * N_ * 64;
    const __nv_bfloat16* Ql = g_qs[1] + (long)bh * N_ * 64;
    const __nv_bfloat16* Kh = g_ks[0] + (long)bh * N_ * 64;
    const __nv_bfloat16* Kl = g_ks[1] + (long)bh * N_ * 64;
    const __nv_bfloat16* Vh = g_vs[0] + (long)bh * N_ * 64;
    const __nv_bfloat16* Vl = g_vs[1] + (long)bh * N_ * 64;

    {
        __nv_bfloat16* Q0 = (__nv_bfloat16*)asw;
        __nv_bfloat16* Q1 = (__nv_bfloat16*)((char*)asw + 18432);
        for (int idx = tid; idx < 128 * 8; idx += 256) {
            int r = idx >> 3, c = idx & 7;
            int qi = q0g + r;
            uint4 vh = make_uint4(0, 0, 0, 0), vl = vh;
            if (qi < N_) {
                vh = *(const uint4*)(Qh + (long)qi * 64 + c * 8);
                vl = *(const uint4*)(Ql + (long)qi * 64 + c * 8);
            }
            *(uint4*)(Q0 + r * 72 + c * 8) = vh;
            *(uint4*)(Q1 + r * 72 + c * 8) = vl;
        }
    }

    float accD[8][4];
    #pragma unroll
    for (int dt = 0; dt < 8; dt++)
        #pragma unroll
        for (int r = 0; r < 4; r++) accD[dt][r] = 0.f;
    float m2[2] = {-INFINITY, -INFINITY};
    float l2[2] = {0.f, 0.f};

    const int rlo = q0g + wid * 16;
    const bool w_dead = (rlo >= N_);
    bool wq_uni = false; int wqb = -2;
    int wblk_lo = 5, wblk_hi = -5;
    if (!w_dead) {
        int rhi = min(rlo + 15, N_ - 1);
        int blo = (max(rlo, 1) - 1) >> 8;
        int bhi = (rhi >= 1) ? ((rhi - 1) >> 8) : -1;
        wblk_lo = blo; wblk_hi = bhi;
        if (rlo >= 1 && blo == bhi) { wq_uni = true; wqb = blo; }
    }
    const int row0g = rlo + gid, row1g = rlo + gid + 8;
    const int qb0 = (row0g >= 1 && row0g < N_) ? ((row0g - 1) >> 8) : -1;
    const int qb1 = (row1g >= 1 && row1g < N_) ? ((row1g - 1) >> 8) : -1;

    auto stagea = [&](int kt_, int bufi) {
        const int k0 = kt_ * 64;
        const uint32_t sb = smb + QREG_B + bufi * STAGE_A;
        const __nv_bfloat16* srcs[4] = {Kh, Kl, Vh, Vl};
        #pragma unroll
        for (int t = 0; t < 8; t++) {
            int idx = tid + t * 256;
            int a = idx >> 9, r = (idx >> 3) & 63, c = idx & 7;
            int kj = k0 + r;
            const __nv_bfloat16* src = srcs[a] + (long)kj * 64 + c * 8;
            cpa16(sb + a * TILE_A + r * 144 + c * 16, src, (kj < N_) ? 16 : 0);
        }
    };

    stagea(0, 0);
    CP_COMMIT();
    __syncthreads();

    for (int kt = 0; kt < 17; kt++) {
        const int k0g = kt * 64;
        __syncthreads();
        if (kt + 1 < 17) stagea(kt + 1, (kt + 1) & 1);
        CP_COMMIT();
        CP_WAIT1();
        __syncthreads();

        bool skip = w_dead;
        bool need_mask = false;
        if (!skip) {
            int klo = max(k0g, 1), khi = min(k0g + 63, N_ - 1);
            int kbl = (klo - 1) >> 8, kbh = (khi - 1) >> 8;
            if (wq_uni && k0g >= 1 && kbl == kbh && kbl == wqb) skip = true;
            else need_mask = (k0g + 63 >= N_) ||
                             (kbl <= wblk_hi && kbh >= wblk_lo);
        }
        if (skip) continue;

        const uint32_t sb = smb + QREG_B + (kt & 1) * STAGE_A;

        float sp[8][4];
        #pragma unroll
        for (int nt = 0; nt < 8; nt++)
            #pragma unroll
            for (int r = 0; r < 4; r++) sp[nt][r] = 0.f;

        #pragma unroll
        for (int ks = 0; ks < 4; ks++) {
            uint32_t qh4[4], ql4[4];
            uint32_t qoff = (uint32_t)((wid * 16 + aro) * 144 + ks * 32 + aco);
            ldsm4(qh4, smb + qoff);
            ldsm4(ql4, smb + 18432 + qoff);
            #pragma unroll
            for (int ntp = 0; ntp < 4; ntp++) {
                uint32_t rowb = (uint32_t)((ntp * 16 + bro) * 144 + ks * 32 + bco);
                uint32_t h4[4], l4[4];
                ldsm4(h4, sb + rowb);
                ldsm4(l4, sb + TILE_A + rowb);
                mma16816(sp[2*ntp], qh4[0], qh4[1], qh4[2], qh4[3], h4[0], h4[1]);
                mma16816(sp[2*ntp], ql4[0], ql4[1], ql4[2], ql4[3], h4[0], h4[1]);
                mma16816(sp[2*ntp], qh4[0], qh4[1], qh4[2], qh4[3], l4[0], l4[1]);
                mma16816(sp[2*ntp+1], qh4[0], qh4[1], qh4[2], qh4[3], h4[2], h4[3]);
                mma16816(sp[2*ntp+1], ql4[0], ql4[1], ql4[2], ql4[3], h4[2], h4[3]);
                mma16816(sp[2*ntp+1], qh4[0], qh4[1], qh4[2], qh4[3], l4[2], l4[3]);
            }
        }

        if (need_mask) {
            #pragma unroll
            for (int nt = 0; nt < 8; nt++) {
                #pragma unroll
                for (int c = 0; c < 4; c++) {
                    int qb = (c >= 2) ? qb1 : qb0;
                    int key = k0g + nt * 8 + 2 * tig + (c & 1);
                    bool bad = (key >= N_) ||
                               (qb >= 0 && key >= 1 && ((key - 1) >> 8) == qb);
                    if (bad) sp[nt][c] = -INFINITY;
                }
            }
        }

        #pragma unroll
        for (int half = 0; half < 2; half++) {
            float mx = -INFINITY;
            #pragma unroll
            for (int nt = 0; nt < 8; nt++)
                mx = fmaxf(mx, fmaxf(sp[nt][half*2], sp[nt][half*2+1]));
            mx = fmaxf(mx, __shfl_xor_sync(0xffffffffu, mx, 1));
            mx = fmaxf(mx, __shfl_xor_sync(0xffffffffu, mx, 2));
            float mnew = fmaxf(m2[half], mx);
            float corr = exp2f(m2[half] - mnew);
            m2[half] = mnew;
            float rs = 0.f;
            #pragma unroll
            for (int nt = 0; nt < 8; nt++) {
                float p0 = exp2f(sp[nt][half*2]   - mnew);
                float p1 = exp2f(sp[nt][half*2+1] - mnew);
                sp[nt][half*2] = p0; sp[nt][half*2+1] = p1;
                rs += p0 + p1;
            }
            rs += __shfl_xor_sync(0xffffffffu, rs, 1);
            rs += __shfl_xor_sync(0xffffffffu, rs, 2);
            l2[half] = l2[half] * corr + rs;
            #pragma unroll
            for (int dt = 0; dt < 8; dt++) {
                accD[dt][half*2]   *= corr;
                accD[dt][half*2+1] *= corr;
            }
        }

        #pragma unroll
        for (int ks = 0; ks < 4; ks++) {
            uint32_t p0[4], p1[4];
            split_pack(sp[2*ks][0],   sp[2*ks][1],   p0[0], p1[0]);
            split_pack(sp[2*ks][2],   sp[2*ks][3],   p0[1], p1[1]);
            split_pack(sp[2*ks+1][0], sp[2*ks+1][1], p0[2], p1[2]);
            split_pack(sp[2*ks+1][2], sp[2*ks+1][3], p0[3], p1[3]);
            #pragma unroll
            for (int dtp = 0; dtp < 4; dtp++) {
                uint32_t rowb = (uint32_t)((ks * 16 + vro) * 144 + dtp * 32 + vco);
                uint32_t h4[4], l4[4];
                ldsm4t(h4, sb + 2 * TILE_A + rowb);
                ldsm4t(l4, sb + 3 * TILE_A + rowb);
                mma16816(accD[2*dtp], p0[0], p0[1], p0[2], p0[3], h4[0], h4[1]);
                mma16816(accD[2*dtp], p1[0], p1[1], p1[2], p1[3], h4[0], h4[1]);
                mma16816(accD[2*dtp], p0[0], p0[1], p0[2], p0[3], l4[0], l4[1]);
                mma16816(accD[2*dtp+1], p0[0], p0[1], p0[2], p0[3], h4[2], h4[3]);
                mma16816(accD[2*dtp+1], p1[0], p1[1], p1[2], p1[3], h4[2], h4[3]);
                mma16816(accD[2*dtp+1], p0[0], p0[1], p0[2], p0[3], l4[2], l4[3]);
            }
        }
    }

    const int b = bh / H_, h = bh % H_;
    #pragma unroll
    for (int half = 0; half < 2; half++) {
        int row = rlo + gid + half * 8;
        if (row < N_) {
            float inv = 1.f / l2[half];
            #pragma unroll
            for (int dt = 0; dt < 8; dt++) {
                int d = dt * 8 + 2 * tig;
                long base = ((long)b * N_ + row) * C_ + h * 64 + d;
                uint32_t hi, lo;
                split_pack(accD[dt][half*2] * inv, accD[dt][half*2+1] * inv, hi, lo);
                *(uint32_t*)&g_cs[0][base] = hi;
                *(uint32_t*)&g_cs[1][base] = lo;
            }
        }
    }
}

// ======================================================================
// cls softmax over precomputed scores (fp64). One CTA per (b,h).
// ======================================================================
__global__ void __launch_bounds__(1024)
cls_soft_kernel() {
    __shared__ double s[N_];
    __shared__ double red[32];
    const int bh = blockIdx.x;
    const int tid = threadIdx.x;
    const int wid = tid >> 5, lane = tid & 31;

    for (int j = tid; j < N_; j += 1024) s[j] = g_cls_s[bh][j];
    __syncthreads();

    double lm = -1e300;
    for (int j = tid; j < N_; j += 1024) lm = fmax(lm, s[j]);
    #pragma unroll
    for (int o = 16; o >= 1; o >>= 1)
        lm = fmax(lm, __shfl_xor_sync(0xffffffffu, lm, o));
    if (lane == 0) red[wid] = lm;
    __syncthreads();
    if (wid == 0) {
        double t = red[lane];
        #pragma unroll
        for (int o = 16; o >= 1; o >>= 1)
            t = fmax(t, __shfl_xor_sync(0xffffffffu, t, o));
        if (lane == 0) red[0] = t;
    }
    __syncthreads();
    const double m = red[0];
    __syncthreads();

    double ls = 0.0;
    for (int j = tid; j < N_; j += 1024) {
        double e = exp(s[j] - m);
        s[j] = e;
        ls += e;
    }
    #pragma unroll
    for (int o = 16; o >= 1; o >>= 1)
        ls += __shfl_xor_sync(0xffffffffu, ls, o);
    if (lane == 0) red[wid] = ls;
    __syncthreads();
    if (wid == 0) {
        double t = red[lane];
        #pragma unroll
        for (int o = 16; o >= 1; o >>= 1)
            t += __shfl_xor_sync(0xffffffffu, t, o);
        if (lane == 0) red[0] = t;
    }
    __syncthreads();
    const double inv = 1.0 / red[0];

    for (int j = tid; j < N_ - 1; j += 1024)
        g_cls_ph[bh][j] = s[j + 1] * inv;
}

// ======================================================================
// head-mean reduce (fp64, h-ascending). One CTA per batch.
// ======================================================================
__global__ void cls_reduce_kernel(float* __restrict__ out) {
    const int b = blockIdx.x, tid = threadIdx.x;
    for (int j = tid; j < N_ - 1; j += 256) {
        double a = 0.0;
        #pragma unroll
        for (int h = 0; h < H_; h++)
            a += g_cls_ph[b * H_ + h][j] * (1.0 / 12.0);
        g_clsd[b * (N_ - 1) + j] = a;
        out[OFF_CLS + (long)b * (N_ - 1) + j] = (float)a;
    }
}

// ======================================================================
// dual bitonic top-k (103 of 1024) on fp64 keys, jax tie-break.
// ======================================================================
__global__ void sort_kernel(float* __restrict__ out) {
    __shared__ double v[1024];
    __shared__ int ix[1024];
    const int b = blockIdx.x, tid = threadIdx.x;

    for (int pass = 0; pass < 2; pass++) {
        __syncthreads();
        for (int i = tid; i < 1024; i += 512) {
            v[i] = g_clsd[b * 1024 + i];
            ix[i] = i;
        }
        __syncthreads();
        const bool desc = (pass == 0);
        for (int k = 2; k <= 1024; k <<= 1) {
            for (int j = k >> 1; j > 0; j >>= 1) {
                for (int i = tid; i < 1024; i += 512) {
                    int p = i ^ j;
                    if (p > i) {
                        double va = v[i], vb = v[p];
                        int ia = ix[i], ib = ix[p];
                        bool ab = desc ? (va > vb || (va == vb && ia < ib))
                                       : (va < vb || (va == vb && ia < ib));
                        bool up = ((i & k) == 0);
                        if (up ? !ab : ab) {
                            v[i] = vb; v[p] = va;
                            ix[i] = ib; ix[p] = ia;
                        }
                    }
                }
                __syncthreads();
            }
        }
        const long offIdx = desc ? OFF_ENH_IDX : OFF_FUSE_IDX;
        const long offBrd = desc ? OFF_ENH_INDEX : OFF_FUSE_INDEX;
        for (int t = tid; t < TOPT; t += 512)
            out[offIdx + (long)b * TOPT + t] = (float)ix[t];
        for (int e = tid; e < TOPT * C_; e += 512) {
            int t = e / C_;
            out[offBrd + ((long)b * TOPT + t) * C_ + (e % C_)] = (float)ix[t];
        }
    }
}

// ======================================================================
// Launch
// ======================================================================
extern "C" void kernel_launch(void* const* d_in, const int* in_sizes, int n_in,
                              void* d_out, int out_size) {
    const float* x     = (const float*)d_in[0];
    const float* w_qkv = (const float*)d_in[1];
    const float* w_out = (const float*)d_in[2];
    const float* b_out = (const float*)d_in[3];
    float* out = (float*)d_out;

    cudaFuncSetAttribute(fused_qkv_cls, cudaFuncAttributeMaxDynamicSharedMemorySize,
                         MMA_SMEM);
    cudaFuncSetAttribute(out_gemm, cudaFuncAttributeMaxDynamicSharedMemorySize,
                         MMA_SMEM);
    cudaFuncSetAttribute(attn_mma, cudaFuncAttributeMaxDynamicSharedMemorySize,
                         ATTN_SMEM3);

    __nv_bfloat16 *xs0, *xs1, *ws0, *ws1, *wo0, *wo1, *cs0, *cs1;
    cudaGetSymbolAddress((void**)&xs0, g_xs); xs1 = xs0 + (long)M_TOT*C_;
    cudaGetSymbolAddress((void**)&ws0, g_ws); ws1 = ws0 + (long)3*C_*C_;
    cudaGetSymbolAddress((void**)&wo0, g_wo); wo1 = wo0 + (long)C_*C_;
    cudaGetSymbolAddress((void**)&cs0, g_cs); cs1 = cs0 + (long)M_TOT*C_;

    split2<<<(M_TOT*C_ + 255)/256, 256>>>(x, xs0, xs1, M_TOT*C_);
    split2<<<(3*C_*C_ + 255)/256, 256>>>(w_qkv, ws0, ws1, 3*C_*C_);
    split2<<<(C_*C_ + 255)/256, 256>>>(w_out, wo0, wo1, C_*C_);

    // fused: cls score chunks (blocks 0..191) + QKV GEMM (192..785)
    fused_qkv_cls<<<CLS_BLOCKS + QKV_BLOCKS, 256, MMA_SMEM>>>(
        xs0, xs1, ws0, ws1, x, w_qkv);

    // attention -> ctx bf16 splits directly
    attn_mma<<<dim3((N_ + 127)/128, B_ * H_), 256, ATTN_SMEM3>>>();

    // OUT: [4100,768] = ctx @ w_out^T + bias
    out_gemm<<<dim3(C_/128, (M_TOT + 127)/128), 256, MMA_SMEM>>>(
        cs0, cs1, wo0, wo1, b_out, out);

    // cls tail: fp64 softmax over precomputed scores, mean, top-k
    cls_soft_kernel<<<B_ * H_, 1024>>>();
    cls_reduce_kernel<<<B_, 256>>>(out);
    sort_kernel<<<B_, 512>>>(out);
}